// round 7
// baseline (speedup 1.0000x reference)
#include <cuda_runtime.h>
#include <cstddef>

#define NA 20000
#define NP 40000
#define EE 400000
#define HID 128
#define NCLS 16

// ----------------------------- scratch (static device globals) -------------------
// Arena: everything zeroed per layer, contiguous -> ONE memset.
#define AR_DEN0   0
#define AR_AGGP0  (3 * NP * 8)
#define AR_AGGP1  (AR_AGGP0 + NP * HID)
#define AR_COLSUM (AR_AGGP1 + NP * HID)
#define AR_TOTAL  (AR_COLSUM + 256)

__device__ float g_arena[AR_TOTAL];
__device__ float g_aggA[NA * HID];          // author aggregation (zeroed at l=0 only)
__device__ float g_auth0[NA * HID];         // x_author @ Wa
__device__ float g_pap[NP * HID];           // paper features after layer-0 combine
__device__ float g_xa[NA * HID];            // xh author
__device__ float g_xp[NP * HID];            // xh paper
__device__ float g_escr0[(size_t)EE * 8];
__device__ float g_escr1[(size_t)EE * 8];
__device__ float g_escr2[(size_t)EE * 8];
__device__ float g_sa0[NA * 8];             // author: writes-src
__device__ float g_sa1[NA * 8];             // author: written_by-dst (l0 only)
__device__ float g_sp0[NP * 8];             // paper: writes-dst
__device__ float g_sp1[NP * 8];             // paper: written_by-src (l0 only)
__device__ float g_sp2[NP * 8];             // paper: cites-src
__device__ float g_sp3[NP * 8];             // paper: cites-dst
__device__ float g_attn[2];
__device__ float g_zb[HID];                 // zero bias

// ----------------------------- helpers -------------------------------------------
__device__ __forceinline__ void atomic_add_f4(float4* addr, float4 v) {
#if __CUDA_ARCH__ >= 900
    atomicAdd(addr, v);   // vector red.global.add.v4.f32
#else
    float* f = (float*)addr;
    atomicAdd(f + 0, v.x); atomicAdd(f + 1, v.y);
    atomicAdd(f + 2, v.z); atomicAdd(f + 3, v.w);
#endif
}

// ----------------------------- SGEMM (R4-proven): C[Mx128]=(relu?)A[MxK]@B+bias ---
// TANH_COLSUM=1: skip C store; accumulate colsum[c] += sum_r tanh(C[r,c]).
// RELUA=1: apply ReLU to A elements while loading (fused activation).
template <int TANH_COLSUM, int RELUA>
__global__ __launch_bounds__(256)
void sgemm_k(const float* __restrict__ A, const float* __restrict__ B,
             const float* __restrict__ bias, float* __restrict__ C,
             float* __restrict__ colsum, int M, int K)
{
    __shared__ alignas(16) float As[8][128];
    __shared__ alignas(16) float Bs[8][128];

    const int tid = threadIdx.x;
    const int tx = tid & 15;         // 16 col groups of 8
    const int ty = tid >> 4;         // 16 row groups of 8
    const int block_row = blockIdx.x * 128;

    const int a_row = tid >> 1;          // 0..127
    const int a_col = (tid & 1) * 4;     // 0 or 4
    const int b_row = tid >> 5;          // 0..7
    const int b_col = (tid & 31) * 4;    // 0..124

    float acc[8][8];
#pragma unroll
    for (int i = 0; i < 8; i++)
#pragma unroll
        for (int j = 0; j < 8; j++) acc[i][j] = 0.f;

    for (int k0 = 0; k0 < K; k0 += 8) {
        const int gr = block_row + a_row;
        float4 av = make_float4(0.f, 0.f, 0.f, 0.f);
        if (gr < M) av = *(const float4*)(A + (size_t)gr * K + k0 + a_col);
        if constexpr (RELUA) {
            av.x = fmaxf(av.x, 0.f); av.y = fmaxf(av.y, 0.f);
            av.z = fmaxf(av.z, 0.f); av.w = fmaxf(av.w, 0.f);
        }
        As[a_col + 0][a_row] = av.x;
        As[a_col + 1][a_row] = av.y;
        As[a_col + 2][a_row] = av.z;
        As[a_col + 3][a_row] = av.w;
        *(float4*)&Bs[b_row][b_col] =
            *(const float4*)(B + (size_t)(k0 + b_row) * 128 + b_col);
        __syncthreads();

#pragma unroll
        for (int k = 0; k < 8; k++) {
            float4 a0 = *(const float4*)&As[k][ty * 8];
            float4 a1 = *(const float4*)&As[k][ty * 8 + 4];
            float4 b0 = *(const float4*)&Bs[k][tx * 8];
            float4 b1 = *(const float4*)&Bs[k][tx * 8 + 4];
            float ar[8] = {a0.x, a0.y, a0.z, a0.w, a1.x, a1.y, a1.z, a1.w};
            float br[8] = {b0.x, b0.y, b0.z, b0.w, b1.x, b1.y, b1.z, b1.w};
#pragma unroll
            for (int i = 0; i < 8; i++)
#pragma unroll
                for (int j = 0; j < 8; j++)
                    acc[i][j] = fmaf(ar[i], br[j], acc[i][j]);
        }
        __syncthreads();
    }

    float bc[8];
#pragma unroll
    for (int j = 0; j < 8; j++) bc[j] = __ldg(&bias[tx * 8 + j]);

    if constexpr (TANH_COLSUM) {
        __shared__ float red[128];
        if (tid < 128) red[tid] = 0.f;
        __syncthreads();
        float cs[8];
#pragma unroll
        for (int j = 0; j < 8; j++) cs[j] = 0.f;
#pragma unroll
        for (int i = 0; i < 8; i++) {
            const int r = block_row + ty * 8 + i;
            if (r < M) {
#pragma unroll
                for (int j = 0; j < 8; j++)
                    cs[j] += tanhf(acc[i][j] + bc[j]);
            }
        }
#pragma unroll
        for (int j = 0; j < 8; j++) atomicAdd(&red[tx * 8 + j], cs[j]);
        __syncthreads();
        if (tid < 128) atomicAdd(&colsum[tid], red[tid]);
    } else {
#pragma unroll
        for (int i = 0; i < 8; i++) {
            const int r = block_row + ty * 8 + i;
            if (r < M) {
                float4 v0 = make_float4(acc[i][0] + bc[0], acc[i][1] + bc[1],
                                        acc[i][2] + bc[2], acc[i][3] + bc[3]);
                float4 v1 = make_float4(acc[i][4] + bc[4], acc[i][5] + bc[5],
                                        acc[i][6] + bc[6], acc[i][7] + bc[7]);
                *(float4*)(C + (size_t)r * 128 + tx * 8)     = v0;
                *(float4*)(C + (size_t)r * 128 + tx * 8 + 4) = v1;
            }
        }
    }
}

// ----------------------------- per-node attention scores --------------------------
// out[n*8+h] = dot(xh[n, h*16 : h*16+16], att[h*16 : h*16+16])
__global__ void att_scores_k(const float* __restrict__ xh, const float* __restrict__ att,
                             float* __restrict__ out, int N)
{
    const int t = blockIdx.x * blockDim.x + threadIdx.x;
    if (t >= N * 8) return;
    const int n = t >> 3, h = t & 7;
    const float4* xr = (const float4*)(xh + (size_t)n * HID + h * 16);
    const float4* ar = (const float4*)(att + h * 16);
    float s = 0.f;
#pragma unroll
    for (int i = 0; i < 4; i++) {
        float4 a = __ldg(&xr[i]);
        float4 b = __ldg(&ar[i]);
        s += a.x * b.x + a.y * b.y + a.z * b.z + a.w * b.w;
    }
    out[t] = s;
}

// ----------------------------- edge pass A (edge types via blockIdx.y) ------------
struct PA {
    const int* ei[3];
    const float* asc[3];
    const float* adc[3];
    float* escr[3];
    float* den[3];
};

__global__ void passA_k(PA p)
{
    const int y = blockIdx.y;
    const int e = blockIdx.x * blockDim.x + threadIdx.x;
    if (e >= EE) return;
    const int* ei = p.ei[y];
    const int si = __ldg(&ei[e]);
    const int di = __ldg(&ei[EE + e]);
    const float4* sp = (const float4*)(p.asc[y] + (size_t)si * 8);
    const float4* dp = (const float4*)(p.adc[y] + (size_t)di * 8);
    float4 s0 = __ldg(&sp[0]), s1 = __ldg(&sp[1]);
    float4 d0 = __ldg(&dp[0]), d1 = __ldg(&dp[1]);
    float v[8] = {s0.x + d0.x, s0.y + d0.y, s0.z + d0.z, s0.w + d0.w,
                  s1.x + d1.x, s1.y + d1.y, s1.z + d1.z, s1.w + d1.w};
#pragma unroll
    for (int i = 0; i < 8; i++) {
        float a = v[i];
        a = (a >= 0.f) ? a : 0.2f * a;   // leaky_relu; exp(leaky) can't overflow here
        v[i] = __expf(a);
    }
    float4 e0 = make_float4(v[0], v[1], v[2], v[3]);
    float4 e1 = make_float4(v[4], v[5], v[6], v[7]);
    ((float4*)p.escr[y])[(size_t)e * 2]     = e0;
    ((float4*)p.escr[y])[(size_t)e * 2 + 1] = e1;
    atomic_add_f4((float4*)(p.den[y] + (size_t)di * 8),     e0);
    atomic_add_f4((float4*)(p.den[y] + (size_t)di * 8) + 1, e1);
}

// ----------------------------- edge pass B (edge types via blockIdx.y) ------------
struct PB {
    const int* ei[3];
    const float* xs[3];
    const float* escr[3];
    const float* den[3];
    float* agg[3];
};

__global__ void passB_k(PB p)
{
    const int y = blockIdx.y;
    const int gt = blockIdx.x * blockDim.x + threadIdx.x;
    const int e = gt >> 5;
    if (e >= EE) return;
    const int lane = gt & 31;
    const int* ei = p.ei[y];
    const int si = __ldg(&ei[e]);
    const int di = __ldg(&ei[EE + e]);
    const int h = lane >> 2;
    const float w = __ldg(&p.escr[y][(size_t)e * 8 + h]) /
                    (__ldg(&p.den[y][(size_t)di * 8 + h]) + 1e-16f);
    float4 v = __ldg(((const float4*)p.xs[y]) + (size_t)si * 32 + lane);
    v.x *= w; v.y *= w; v.z *= w; v.w *= w;
    atomic_add_f4(((float4*)p.agg[y]) + (size_t)di * 32 + lane, v);
}

// ----------------------------- semantic attention weights (M=2) --------------------
__global__ void sem_attn_k(const float* __restrict__ colsum, const float* __restrict__ q,
                           float* __restrict__ attn)
{
    __shared__ float r0[128], r1[128];
    const int t = threadIdx.x;
    const float qv = q[t];
    r0[t] = qv * colsum[t];
    r1[t] = qv * colsum[128 + t];
    __syncthreads();
    for (int s = 64; s > 0; s >>= 1) {
        if (t < s) { r0[t] += r0[t + s]; r1[t] += r1[t + s]; }
        __syncthreads();
    }
    if (t == 0) {
        const float s0 = r0[0] / (float)NP;
        const float s1 = r1[0] / (float)NP;
        const float m = fmaxf(s0, s1);
        const float e0 = __expf(s0 - m), e1 = __expf(s1 - m);
        const float inv = 1.f / (e0 + e1);
        attn[0] = e0 * inv;
        attn[1] = e1 * inv;
    }
}

// ----------------------------- combine (layer-0): pap = a0*relu(s0)+a1*relu(s1) ----
__global__ void combine_k(float4* __restrict__ out, const float4* __restrict__ s0,
                          const float4* __restrict__ s1, const float* __restrict__ attn,
                          int n4)
{
    const int i = blockIdx.x * blockDim.x + threadIdx.x;
    if (i >= n4) return;
    const float a0 = __ldg(&attn[0]);
    const float a1 = __ldg(&attn[1]);
    float4 x = __ldg(&s0[i]);
    float4 y = __ldg(&s1[i]);
    x.x = fmaxf(x.x, 0.f); x.y = fmaxf(x.y, 0.f);
    x.z = fmaxf(x.z, 0.f); x.w = fmaxf(x.w, 0.f);
    y.x = fmaxf(y.x, 0.f); y.y = fmaxf(y.y, 0.f);
    y.z = fmaxf(y.z, 0.f); y.w = fmaxf(y.w, 0.f);
    out[i] = make_float4(a0 * x.x + a1 * y.x, a0 * x.y + a1 * y.y,
                         a0 * x.z + a1 * y.z, a0 * x.w + a1 * y.w);
}

// ----------------------------- final linear (fused layer-1 combine + relu) ---------
__global__ __launch_bounds__(256)
void final_lin_k(const float* __restrict__ s0, const float* __restrict__ s1,
                 const float* __restrict__ attn, const float* __restrict__ W,
                 const float* __restrict__ b, float* __restrict__ out)
{
    __shared__ float Ws[128 * NCLS];
    for (int i = threadIdx.x; i < 128 * NCLS; i += blockDim.x) Ws[i] = W[i];
    __syncthreads();
    const int n = blockIdx.x * blockDim.x + threadIdx.x;
    if (n >= NP) return;
    const float a0 = __ldg(&attn[0]);
    const float a1 = __ldg(&attn[1]);
    float acc[NCLS];
#pragma unroll
    for (int c = 0; c < NCLS; c++) acc[c] = __ldg(&b[c]);
    const float4* x0 = (const float4*)(s0 + (size_t)n * 128);
    const float4* x1 = (const float4*)(s1 + (size_t)n * 128);
#pragma unroll
    for (int k4 = 0; k4 < 32; k4++) {
        float4 u = __ldg(&x0[k4]);
        float4 v = __ldg(&x1[k4]);
        const float xs[4] = {
            a0 * fmaxf(u.x, 0.f) + a1 * fmaxf(v.x, 0.f),
            a0 * fmaxf(u.y, 0.f) + a1 * fmaxf(v.y, 0.f),
            a0 * fmaxf(u.z, 0.f) + a1 * fmaxf(v.z, 0.f),
            a0 * fmaxf(u.w, 0.f) + a1 * fmaxf(v.w, 0.f)};
#pragma unroll
        for (int uu = 0; uu < 4; uu++) {
            const int k = k4 * 4 + uu;
#pragma unroll
            for (int c = 0; c < NCLS; c++)
                acc[c] = fmaf(xs[uu], Ws[k * NCLS + c], acc[c]);
        }
    }
    float4* op = (float4*)(out + (size_t)n * NCLS);
#pragma unroll
    for (int c4 = 0; c4 < 4; c4++)
        op[c4] = make_float4(acc[c4 * 4], acc[c4 * 4 + 1], acc[c4 * 4 + 2], acc[c4 * 4 + 3]);
}

// ----------------------------- host orchestration ----------------------------------
extern "C" void kernel_launch(void* const* d_in, const int* in_sizes, int n_in,
                              void* d_out, int out_size)
{
    const float* x_author = (const float*)d_in[0];
    const float* x_paper  = (const float*)d_in[1];
    const float* Wa       = (const float*)d_in[2];
    const float* proj_w   = (const float*)d_in[3];
    const float* proj_b   = (const float*)d_in[4];
    const float* att_src  = (const float*)d_in[5];
    const float* att_dst  = (const float*)d_in[6];
    const float* klin_w   = (const float*)d_in[7];
    const float* klin_b   = (const float*)d_in[8];
    const float* q        = (const float*)d_in[9];
    const float* lin_w    = (const float*)d_in[10];
    const float* lin_b    = (const float*)d_in[11];
    const int*   ei_w     = (const int*)d_in[12];
    const int*   ei_wb    = (const int*)d_in[13];
    const int*   ei_c     = (const int*)d_in[14];
    float* out = (float*)d_out;

    float *arena, *aggA, *auth0, *pap, *xa, *xp;
    float *escr0, *escr1, *escr2;
    float *sa0, *sa1, *sp0, *sp1, *sp2, *sp3, *attn, *zb;
    cudaGetSymbolAddress((void**)&arena, g_arena);
    cudaGetSymbolAddress((void**)&aggA, g_aggA);
    cudaGetSymbolAddress((void**)&auth0, g_auth0);
    cudaGetSymbolAddress((void**)&pap, g_pap);
    cudaGetSymbolAddress((void**)&xa, g_xa);
    cudaGetSymbolAddress((void**)&xp, g_xp);
    cudaGetSymbolAddress((void**)&escr0, g_escr0);
    cudaGetSymbolAddress((void**)&escr1, g_escr1);
    cudaGetSymbolAddress((void**)&escr2, g_escr2);
    cudaGetSymbolAddress((void**)&sa0, g_sa0);
    cudaGetSymbolAddress((void**)&sa1, g_sa1);
    cudaGetSymbolAddress((void**)&sp0, g_sp0);
    cudaGetSymbolAddress((void**)&sp1, g_sp1);
    cudaGetSymbolAddress((void**)&sp2, g_sp2);
    cudaGetSymbolAddress((void**)&sp3, g_sp3);
    cudaGetSymbolAddress((void**)&attn, g_attn);
    cudaGetSymbolAddress((void**)&zb, g_zb);

    float* den0 = arena + AR_DEN0;
    float* den1 = arena + NP * 8;
    float* den2 = arena + 2 * NP * 8;
    float* aggP0 = arena + AR_AGGP0;
    float* aggP1 = arena + AR_AGGP1;
    float* colsum = arena + AR_COLSUM;

    // author raw projection: [20000,64] @ [64,128] (no bias)
    sgemm_k<0, 0><<<(NA + 127) / 128, 256>>>(x_author, Wa, zb, auth0, nullptr, NA, 64);

    // =============================== layer 0 ===============================
    cudaMemsetAsync(arena, 0, (size_t)AR_TOTAL * sizeof(float));
    cudaMemsetAsync(aggA, 0, (size_t)NA * HID * sizeof(float));

    sgemm_k<0, 0><<<(NA + 127) / 128, 256>>>(
        auth0, proj_w, proj_b, xa, nullptr, NA, 128);
    sgemm_k<0, 0><<<(NP + 127) / 128, 256>>>(
        x_paper, proj_w + (size_t)128 * 128, proj_b + 128, xp, nullptr, NP, 128);

    // attention scores (6 tiny kernels)
    att_scores_k<<<(NA * 8 + 255) / 256, 256>>>(xa, att_src + 0 * 128, sa0, NA);
    att_scores_k<<<(NA * 8 + 255) / 256, 256>>>(xa, att_dst + 1 * 128, sa1, NA);
    att_scores_k<<<(NP * 8 + 255) / 256, 256>>>(xp, att_dst + 0 * 128, sp0, NP);
    att_scores_k<<<(NP * 8 + 255) / 256, 256>>>(xp, att_src + 1 * 128, sp1, NP);
    att_scores_k<<<(NP * 8 + 255) / 256, 256>>>(xp, att_src + 2 * 128, sp2, NP);
    att_scores_k<<<(NP * 8 + 255) / 256, 256>>>(xp, att_dst + 2 * 128, sp3, NP);

    {
        PA pa;
        pa.ei[0] = ei_w;  pa.asc[0] = sa0; pa.adc[0] = sp0; pa.escr[0] = escr0; pa.den[0] = den0;
        pa.ei[1] = ei_wb; pa.asc[1] = sp1; pa.adc[1] = sa1; pa.escr[1] = escr1; pa.den[1] = den1;
        pa.ei[2] = ei_c;  pa.asc[2] = sp2; pa.adc[2] = sp3; pa.escr[2] = escr2; pa.den[2] = den2;
        passA_k<<<dim3((EE + 255) / 256, 3), 256>>>(pa);

        PB pb;
        pb.ei[0] = ei_w;  pb.xs[0] = xa; pb.escr[0] = escr0; pb.den[0] = den0; pb.agg[0] = aggP0;
        pb.ei[1] = ei_wb; pb.xs[1] = xp; pb.escr[1] = escr1; pb.den[1] = den1; pb.agg[1] = aggA;
        pb.ei[2] = ei_c;  pb.xs[2] = xp; pb.escr[2] = escr2; pb.den[2] = den2; pb.agg[2] = aggP1;
        passB_k<<<dim3((EE * 32 + 255) / 256, 3), 256>>>(pb);
    }

    // semantic attention (relu fused into tanh-gemm A-load)
    sgemm_k<1, 1><<<(NP + 127) / 128, 256>>>(
        aggP0, klin_w, klin_b, nullptr, colsum, NP, 128);
    sgemm_k<1, 1><<<(NP + 127) / 128, 256>>>(
        aggP1, klin_w, klin_b, nullptr, colsum + 128, NP, 128);
    sem_attn_k<<<1, 128>>>(colsum, q, attn);
    combine_k<<<(NP * 32 + 255) / 256, 256>>>(
        (float4*)pap, (const float4*)aggP0, (const float4*)aggP1, attn, NP * 32);

    // =============================== layer 1 ===============================
    // written_by chain is dead at the last layer (author output never read).
    cudaMemsetAsync(arena, 0, (size_t)AR_TOTAL * sizeof(float));

    sgemm_k<0, 1><<<(NA + 127) / 128, 256>>>(
        aggA, proj_w + (size_t)2 * 128 * 128, proj_b + 2 * 128, xa, nullptr, NA, 128);
    sgemm_k<0, 0><<<(NP + 127) / 128, 256>>>(
        pap, proj_w + (size_t)3 * 128 * 128, proj_b + 3 * 128, xp, nullptr, NP, 128);

    att_scores_k<<<(NA * 8 + 255) / 256, 256>>>(xa, att_src + 3 * 128, sa0, NA);
    att_scores_k<<<(NP * 8 + 255) / 256, 256>>>(xp, att_dst + 3 * 128, sp0, NP);
    att_scores_k<<<(NP * 8 + 255) / 256, 256>>>(xp, att_src + 5 * 128, sp2, NP);
    att_scores_k<<<(NP * 8 + 255) / 256, 256>>>(xp, att_dst + 5 * 128, sp3, NP);

    {
        PA pa;
        pa.ei[0] = ei_w; pa.asc[0] = sa0; pa.adc[0] = sp0; pa.escr[0] = escr0; pa.den[0] = den0;
        pa.ei[1] = ei_c; pa.asc[1] = sp2; pa.adc[1] = sp3; pa.escr[1] = escr2; pa.den[1] = den2;
        pa.ei[2] = pa.ei[1]; pa.asc[2] = pa.asc[1]; pa.adc[2] = pa.adc[1];
        pa.escr[2] = pa.escr[1]; pa.den[2] = pa.den[1];
        passA_k<<<dim3((EE + 255) / 256, 2), 256>>>(pa);

        PB pb;
        pb.ei[0] = ei_w; pb.xs[0] = xa; pb.escr[0] = escr0; pb.den[0] = den0; pb.agg[0] = aggP0;
        pb.ei[1] = ei_c; pb.xs[1] = xp; pb.escr[1] = escr2; pb.den[1] = den2; pb.agg[1] = aggP1;
        pb.ei[2] = pb.ei[1]; pb.xs[2] = pb.xs[1]; pb.escr[2] = pb.escr[1];
        pb.den[2] = pb.den[1]; pb.agg[2] = pb.agg[1];
        passB_k<<<dim3((EE * 32 + 255) / 256, 2), 256>>>(pb);
    }

    sgemm_k<1, 1><<<(NP + 127) / 128, 256>>>(
        aggP0, klin_w + (size_t)128 * 128, klin_b + 128, nullptr, colsum, NP, 128);
    sgemm_k<1, 1><<<(NP + 127) / 128, 256>>>(
        aggP1, klin_w + (size_t)128 * 128, klin_b + 128, nullptr, colsum + 128, NP, 128);
    sem_attn_k<<<1, 128>>>(colsum, q + 128, attn);

    // final linear with fused layer-1 combine + relu
    final_lin_k<<<(NP + 255) / 256, 256>>>(aggP0, aggP1, attn, lin_w, lin_b, out);
}

// round 8
// speedup vs baseline: 1.8521x; 1.8521x over previous
#include <cuda_runtime.h>
#include <cstddef>

#define NA 20000
#define NP 40000
#define EE 400000
#define HID 128
#define NCLS 16

// ----------------------------- scratch (static device globals) -------------------
// Sequential edge-phase processing: ONE escr + ONE denom buffer, reused.
// Keeps each phase's random-access working set (~45MB) L2-resident (L2=126MB).
__device__ float g_auth0[NA * HID];         // x_author @ Wa
__device__ float g_aggA[NA * HID];          // author aggregation (written_by, l0)
__device__ float g_pap[NP * HID];           // paper features after layer-0 combine
__device__ float g_xa[NA * HID];            // xh author
__device__ float g_xp[NP * HID];            // xh paper
__device__ float g_aggP0[NP * HID];
__device__ float g_aggP1[NP * HID];
__device__ float g_escr[(size_t)EE * 8];
__device__ float g_denom[NP * 8];
__device__ float g_sa0[NA * 8];
__device__ float g_sa1[NA * 8];
__device__ float g_sp0[NP * 8];
__device__ float g_sp1[NP * 8];
__device__ float g_sp2[NP * 8];
__device__ float g_sp3[NP * 8];
__device__ float g_colsum[2 * HID];
__device__ float g_attn[2];
__device__ float g_zb[HID];                 // zero bias

// ----------------------------- helpers -------------------------------------------
__device__ __forceinline__ void atomic_add_f4(float4* addr, float4 v) {
#if __CUDA_ARCH__ >= 900
    atomicAdd(addr, v);   // vector red.global.add.v4.f32
#else
    float* f = (float*)addr;
    atomicAdd(f + 0, v.x); atomicAdd(f + 1, v.y);
    atomicAdd(f + 2, v.z); atomicAdd(f + 3, v.w);
#endif
}

// ----------------------------- SGEMM (R4-proven): C[Mx128]=(relu?)A[MxK]@B+bias ---
// TANH_COLSUM=1: skip C store; accumulate colsum[c] += sum_r tanh(C[r,c]).
// RELUA=1: apply ReLU to A elements while loading (fused activation).
template <int TANH_COLSUM, int RELUA>
__global__ __launch_bounds__(256)
void sgemm_k(const float* __restrict__ A, const float* __restrict__ B,
             const float* __restrict__ bias, float* __restrict__ C,
             float* __restrict__ colsum, int M, int K)
{
    __shared__ alignas(16) float As[8][128];
    __shared__ alignas(16) float Bs[8][128];

    const int tid = threadIdx.x;
    const int tx = tid & 15;
    const int ty = tid >> 4;
    const int block_row = blockIdx.x * 128;

    const int a_row = tid >> 1;
    const int a_col = (tid & 1) * 4;
    const int b_row = tid >> 5;
    const int b_col = (tid & 31) * 4;

    float acc[8][8];
#pragma unroll
    for (int i = 0; i < 8; i++)
#pragma unroll
        for (int j = 0; j < 8; j++) acc[i][j] = 0.f;

    for (int k0 = 0; k0 < K; k0 += 8) {
        const int gr = block_row + a_row;
        float4 av = make_float4(0.f, 0.f, 0.f, 0.f);
        if (gr < M) av = *(const float4*)(A + (size_t)gr * K + k0 + a_col);
        if constexpr (RELUA) {
            av.x = fmaxf(av.x, 0.f); av.y = fmaxf(av.y, 0.f);
            av.z = fmaxf(av.z, 0.f); av.w = fmaxf(av.w, 0.f);
        }
        As[a_col + 0][a_row] = av.x;
        As[a_col + 1][a_row] = av.y;
        As[a_col + 2][a_row] = av.z;
        As[a_col + 3][a_row] = av.w;
        *(float4*)&Bs[b_row][b_col] =
            *(const float4*)(B + (size_t)(k0 + b_row) * 128 + b_col);
        __syncthreads();

#pragma unroll
        for (int k = 0; k < 8; k++) {
            float4 a0 = *(const float4*)&As[k][ty * 8];
            float4 a1 = *(const float4*)&As[k][ty * 8 + 4];
            float4 b0 = *(const float4*)&Bs[k][tx * 8];
            float4 b1 = *(const float4*)&Bs[k][tx * 8 + 4];
            float ar[8] = {a0.x, a0.y, a0.z, a0.w, a1.x, a1.y, a1.z, a1.w};
            float br[8] = {b0.x, b0.y, b0.z, b0.w, b1.x, b1.y, b1.z, b1.w};
#pragma unroll
            for (int i = 0; i < 8; i++)
#pragma unroll
                for (int j = 0; j < 8; j++)
                    acc[i][j] = fmaf(ar[i], br[j], acc[i][j]);
        }
        __syncthreads();
    }

    float bc[8];
#pragma unroll
    for (int j = 0; j < 8; j++) bc[j] = __ldg(&bias[tx * 8 + j]);

    if constexpr (TANH_COLSUM) {
        __shared__ float red[128];
        if (tid < 128) red[tid] = 0.f;
        __syncthreads();
        float cs[8];
#pragma unroll
        for (int j = 0; j < 8; j++) cs[j] = 0.f;
#pragma unroll
        for (int i = 0; i < 8; i++) {
            const int r = block_row + ty * 8 + i;
            if (r < M) {
#pragma unroll
                for (int j = 0; j < 8; j++)
                    cs[j] += tanhf(acc[i][j] + bc[j]);
            }
        }
#pragma unroll
        for (int j = 0; j < 8; j++) atomicAdd(&red[tx * 8 + j], cs[j]);
        __syncthreads();
        if (tid < 128) atomicAdd(&colsum[tid], red[tid]);
    } else {
#pragma unroll
        for (int i = 0; i < 8; i++) {
            const int r = block_row + ty * 8 + i;
            if (r < M) {
                float4 v0 = make_float4(acc[i][0] + bc[0], acc[i][1] + bc[1],
                                        acc[i][2] + bc[2], acc[i][3] + bc[3]);
                float4 v1 = make_float4(acc[i][4] + bc[4], acc[i][5] + bc[5],
                                        acc[i][6] + bc[6], acc[i][7] + bc[7]);
                *(float4*)(C + (size_t)r * 128 + tx * 8)     = v0;
                *(float4*)(C + (size_t)r * 128 + tx * 8 + 4) = v1;
            }
        }
    }
}

// ----------------------------- multi attention scores (1 xh pass, <=4 scores) -----
// out[s][n*8+h] = dot(xh[n, 16h:16h+16], att[s][16h:16h+16])
struct MS { const float* att[4]; float* out[4]; int nsc; };

__global__ void att_multi_k(const float* __restrict__ xh, MS ms, int N)
{
    const int t = blockIdx.x * blockDim.x + threadIdx.x;
    if (t >= N * 8) return;
    const int n = t >> 3, h = t & 7;
    const float4* xr = (const float4*)(xh + (size_t)n * HID + h * 16);
    float4 x0 = __ldg(&xr[0]), x1 = __ldg(&xr[1]);
    float4 x2 = __ldg(&xr[2]), x3 = __ldg(&xr[3]);
#pragma unroll
    for (int s = 0; s < 4; s++) {
        if (s < ms.nsc) {
            const float4* ar = (const float4*)(ms.att[s] + h * 16);
            float4 a0 = __ldg(&ar[0]), a1 = __ldg(&ar[1]);
            float4 a2 = __ldg(&ar[2]), a3 = __ldg(&ar[3]);
            float r = x0.x * a0.x + x0.y * a0.y + x0.z * a0.z + x0.w * a0.w
                    + x1.x * a1.x + x1.y * a1.y + x1.z * a1.z + x1.w * a1.w
                    + x2.x * a2.x + x2.y * a2.y + x2.z * a2.z + x2.w * a2.w
                    + x3.x * a3.x + x3.y * a3.y + x3.z * a3.z + x3.w * a3.w;
            ms.out[s][t] = r;
        }
    }
}

// ----------------------------- edge pass A (single edge type; R4-proven) ----------
__global__ void edge_passA(const int* __restrict__ ei, const float* __restrict__ asrc,
                           const float* __restrict__ adst, float* __restrict__ escr,
                           float* __restrict__ denom)
{
    const int e = blockIdx.x * blockDim.x + threadIdx.x;
    if (e >= EE) return;
    const int si = __ldg(&ei[e]);
    const int di = __ldg(&ei[EE + e]);
    const float4* sp = (const float4*)(asrc + (size_t)si * 8);
    const float4* dp = (const float4*)(adst + (size_t)di * 8);
    float4 s0 = __ldg(&sp[0]), s1 = __ldg(&sp[1]);
    float4 d0 = __ldg(&dp[0]), d1 = __ldg(&dp[1]);
    float v[8] = {s0.x + d0.x, s0.y + d0.y, s0.z + d0.z, s0.w + d0.w,
                  s1.x + d1.x, s1.y + d1.y, s1.z + d1.z, s1.w + d1.w};
#pragma unroll
    for (int i = 0; i < 8; i++) {
        float a = v[i];
        a = (a >= 0.f) ? a : 0.2f * a;   // leaky_relu; exp can't overflow at these scales
        v[i] = __expf(a);
    }
    float4 e0 = make_float4(v[0], v[1], v[2], v[3]);
    float4 e1 = make_float4(v[4], v[5], v[6], v[7]);
    ((float4*)escr)[(size_t)e * 2]     = e0;
    ((float4*)escr)[(size_t)e * 2 + 1] = e1;
    atomic_add_f4((float4*)(denom + (size_t)di * 8),     e0);
    atomic_add_f4((float4*)(denom + (size_t)di * 8) + 1, e1);
}

// ----------------------------- edge pass B (single edge type; R4-proven) ----------
__global__ void edge_passB(const int* __restrict__ ei, const float* __restrict__ xh_src,
                           const float* __restrict__ escr, const float* __restrict__ denom,
                           float* __restrict__ agg)
{
    const int gt = blockIdx.x * blockDim.x + threadIdx.x;
    const int e = gt >> 5;
    if (e >= EE) return;
    const int lane = gt & 31;
    const int si = __ldg(&ei[e]);
    const int di = __ldg(&ei[EE + e]);
    const int h = lane >> 2;
    const float w = __ldg(&escr[(size_t)e * 8 + h]) /
                    (__ldg(&denom[(size_t)di * 8 + h]) + 1e-16f);
    float4 v = __ldg(((const float4*)xh_src) + (size_t)si * 32 + lane);
    v.x *= w; v.y *= w; v.z *= w; v.w *= w;
    atomic_add_f4(((float4*)agg) + (size_t)di * 32 + lane, v);
}

// ----------------------------- semantic attention weights (M=2) --------------------
__global__ void sem_attn_k(const float* __restrict__ colsum, const float* __restrict__ q,
                           float* __restrict__ attn)
{
    __shared__ float r0[128], r1[128];
    const int t = threadIdx.x;
    const float qv = q[t];
    r0[t] = qv * colsum[t];
    r1[t] = qv * colsum[128 + t];
    __syncthreads();
    for (int s = 64; s > 0; s >>= 1) {
        if (t < s) { r0[t] += r0[t + s]; r1[t] += r1[t + s]; }
        __syncthreads();
    }
    if (t == 0) {
        const float s0 = r0[0] / (float)NP;
        const float s1 = r1[0] / (float)NP;
        const float m = fmaxf(s0, s1);
        const float e0 = __expf(s0 - m), e1 = __expf(s1 - m);
        const float inv = 1.f / (e0 + e1);
        attn[0] = e0 * inv;
        attn[1] = e1 * inv;
    }
}

// ----------------------------- combine (layer-0): pap = a0*relu(s0)+a1*relu(s1) ----
__global__ void combine_k(float4* __restrict__ out, const float4* __restrict__ s0,
                          const float4* __restrict__ s1, const float* __restrict__ attn,
                          int n4)
{
    const int i = blockIdx.x * blockDim.x + threadIdx.x;
    if (i >= n4) return;
    const float a0 = __ldg(&attn[0]);
    const float a1 = __ldg(&attn[1]);
    float4 x = __ldg(&s0[i]);
    float4 y = __ldg(&s1[i]);
    x.x = fmaxf(x.x, 0.f); x.y = fmaxf(x.y, 0.f);
    x.z = fmaxf(x.z, 0.f); x.w = fmaxf(x.w, 0.f);
    y.x = fmaxf(y.x, 0.f); y.y = fmaxf(y.y, 0.f);
    y.z = fmaxf(y.z, 0.f); y.w = fmaxf(y.w, 0.f);
    out[i] = make_float4(a0 * x.x + a1 * y.x, a0 * x.y + a1 * y.y,
                         a0 * x.z + a1 * y.z, a0 * x.w + a1 * y.w);
}

// ----------------------------- final linear (fused layer-1 combine + relu) ---------
__global__ __launch_bounds__(256)
void final_lin_k(const float* __restrict__ s0, const float* __restrict__ s1,
                 const float* __restrict__ attn, const float* __restrict__ W,
                 const float* __restrict__ b, float* __restrict__ out)
{
    __shared__ float Ws[128 * NCLS];
    for (int i = threadIdx.x; i < 128 * NCLS; i += blockDim.x) Ws[i] = W[i];
    __syncthreads();
    const int n = blockIdx.x * blockDim.x + threadIdx.x;
    if (n >= NP) return;
    const float a0 = __ldg(&attn[0]);
    const float a1 = __ldg(&attn[1]);
    float acc[NCLS];
#pragma unroll
    for (int c = 0; c < NCLS; c++) acc[c] = __ldg(&b[c]);
    const float4* x0 = (const float4*)(s0 + (size_t)n * 128);
    const float4* x1 = (const float4*)(s1 + (size_t)n * 128);
#pragma unroll
    for (int k4 = 0; k4 < 32; k4++) {
        float4 u = __ldg(&x0[k4]);
        float4 v = __ldg(&x1[k4]);
        const float xs[4] = {
            a0 * fmaxf(u.x, 0.f) + a1 * fmaxf(v.x, 0.f),
            a0 * fmaxf(u.y, 0.f) + a1 * fmaxf(v.y, 0.f),
            a0 * fmaxf(u.z, 0.f) + a1 * fmaxf(v.z, 0.f),
            a0 * fmaxf(u.w, 0.f) + a1 * fmaxf(v.w, 0.f)};
#pragma unroll
        for (int uu = 0; uu < 4; uu++) {
            const int k = k4 * 4 + uu;
#pragma unroll
            for (int c = 0; c < NCLS; c++)
                acc[c] = fmaf(xs[uu], Ws[k * NCLS + c], acc[c]);
        }
    }
    float4* op = (float4*)(out + (size_t)n * NCLS);
#pragma unroll
    for (int c4 = 0; c4 < 4; c4++)
        op[c4] = make_float4(acc[c4 * 4], acc[c4 * 4 + 1], acc[c4 * 4 + 2], acc[c4 * 4 + 3]);
}

// ----------------------------- host orchestration ----------------------------------
extern "C" void kernel_launch(void* const* d_in, const int* in_sizes, int n_in,
                              void* d_out, int out_size)
{
    const float* x_author = (const float*)d_in[0];
    const float* x_paper  = (const float*)d_in[1];
    const float* Wa       = (const float*)d_in[2];
    const float* proj_w   = (const float*)d_in[3];
    const float* proj_b   = (const float*)d_in[4];
    const float* att_src  = (const float*)d_in[5];
    const float* att_dst  = (const float*)d_in[6];
    const float* klin_w   = (const float*)d_in[7];
    const float* klin_b   = (const float*)d_in[8];
    const float* q        = (const float*)d_in[9];
    const float* lin_w    = (const float*)d_in[10];
    const float* lin_b    = (const float*)d_in[11];
    const int*   ei_w     = (const int*)d_in[12];
    const int*   ei_wb    = (const int*)d_in[13];
    const int*   ei_c     = (const int*)d_in[14];
    float* out = (float*)d_out;

    float *auth0, *aggA, *pap, *xa, *xp, *aggP0, *aggP1, *escr, *denom;
    float *sa0, *sa1, *sp0, *sp1, *sp2, *sp3, *colsum, *attn, *zb;
    cudaGetSymbolAddress((void**)&auth0, g_auth0);
    cudaGetSymbolAddress((void**)&aggA, g_aggA);
    cudaGetSymbolAddress((void**)&pap, g_pap);
    cudaGetSymbolAddress((void**)&xa, g_xa);
    cudaGetSymbolAddress((void**)&xp, g_xp);
    cudaGetSymbolAddress((void**)&aggP0, g_aggP0);
    cudaGetSymbolAddress((void**)&aggP1, g_aggP1);
    cudaGetSymbolAddress((void**)&escr, g_escr);
    cudaGetSymbolAddress((void**)&denom, g_denom);
    cudaGetSymbolAddress((void**)&sa0, g_sa0);
    cudaGetSymbolAddress((void**)&sa1, g_sa1);
    cudaGetSymbolAddress((void**)&sp0, g_sp0);
    cudaGetSymbolAddress((void**)&sp1, g_sp1);
    cudaGetSymbolAddress((void**)&sp2, g_sp2);
    cudaGetSymbolAddress((void**)&sp3, g_sp3);
    cudaGetSymbolAddress((void**)&colsum, g_colsum);
    cudaGetSymbolAddress((void**)&attn, g_attn);
    cudaGetSymbolAddress((void**)&zb, g_zb);

    // author raw projection: [20000,64] @ [64,128] (no bias)
    sgemm_k<0, 0><<<(NA + 127) / 128, 256>>>(x_author, Wa, zb, auth0, nullptr, NA, 64);

    // =============================== layer 0 ===============================
    sgemm_k<0, 0><<<(NA + 127) / 128, 256>>>(
        auth0, proj_w, proj_b, xa, nullptr, NA, 128);
    sgemm_k<0, 0><<<(NP + 127) / 128, 256>>>(
        x_paper, proj_w + (size_t)128 * 128, proj_b + 128, xp, nullptr, NP, 128);

    {   // author scores: writes-src, written_by-dst  (one xh pass)
        MS ms; ms.nsc = 2;
        ms.att[0] = att_src + 0 * 128; ms.out[0] = sa0;
        ms.att[1] = att_dst + 1 * 128; ms.out[1] = sa1;
        ms.att[2] = ms.att[0]; ms.out[2] = sa0; ms.att[3] = ms.att[0]; ms.out[3] = sa0;
        att_multi_k<<<(NA * 8 + 255) / 256, 256>>>(xa, ms, NA);
    }
    {   // paper scores: writes-dst, wb-src, cites-src, cites-dst (one xh pass)
        MS ms; ms.nsc = 4;
        ms.att[0] = att_dst + 0 * 128; ms.out[0] = sp0;
        ms.att[1] = att_src + 1 * 128; ms.out[1] = sp1;
        ms.att[2] = att_src + 2 * 128; ms.out[2] = sp2;
        ms.att[3] = att_dst + 2 * 128; ms.out[3] = sp3;
        att_multi_k<<<(NP * 8 + 255) / 256, 256>>>(xp, ms, NP);
    }

    // edge type 0: writes (author -> paper), SEQUENTIAL phases (L2-resident WS)
    cudaMemsetAsync(denom, 0, (size_t)NP * 8 * sizeof(float));
    edge_passA<<<(EE + 255) / 256, 256>>>(ei_w, sa0, sp0, escr, denom);
    cudaMemsetAsync(aggP0, 0, (size_t)NP * HID * sizeof(float));
    edge_passB<<<(EE * 32 + 255) / 256, 256>>>(ei_w, xa, escr, denom, aggP0);

    // edge type 1: written_by (paper -> author)
    cudaMemsetAsync(denom, 0, (size_t)NA * 8 * sizeof(float));
    edge_passA<<<(EE + 255) / 256, 256>>>(ei_wb, sp1, sa1, escr, denom);
    cudaMemsetAsync(aggA, 0, (size_t)NA * HID * sizeof(float));
    edge_passB<<<(EE * 32 + 255) / 256, 256>>>(ei_wb, xp, escr, denom, aggA);

    // edge type 2: cites (paper -> paper)
    cudaMemsetAsync(denom, 0, (size_t)NP * 8 * sizeof(float));
    edge_passA<<<(EE + 255) / 256, 256>>>(ei_c, sp2, sp3, escr, denom);
    cudaMemsetAsync(aggP1, 0, (size_t)NP * HID * sizeof(float));
    edge_passB<<<(EE * 32 + 255) / 256, 256>>>(ei_c, xp, escr, denom, aggP1);

    // semantic attention (relu fused into tanh-gemm A-load)
    cudaMemsetAsync(colsum, 0, 2 * 128 * sizeof(float));
    sgemm_k<1, 1><<<(NP + 127) / 128, 256>>>(
        aggP0, klin_w, klin_b, nullptr, colsum, NP, 128);
    sgemm_k<1, 1><<<(NP + 127) / 128, 256>>>(
        aggP1, klin_w, klin_b, nullptr, colsum + 128, NP, 128);
    sem_attn_k<<<1, 128>>>(colsum, q, attn);
    combine_k<<<(NP * 32 + 255) / 256, 256>>>(
        (float4*)pap, (const float4*)aggP0, (const float4*)aggP1, attn, NP * 32);

    // =============================== layer 1 ===============================
    // written_by chain is dead at the last layer (author output never read).
    sgemm_k<0, 1><<<(NA + 127) / 128, 256>>>(     // relu(aggA) fused into A-load
        aggA, proj_w + (size_t)2 * 128 * 128, proj_b + 2 * 128, xa, nullptr, NA, 128);
    sgemm_k<0, 0><<<(NP + 127) / 128, 256>>>(
        pap, proj_w + (size_t)3 * 128 * 128, proj_b + 3 * 128, xp, nullptr, NP, 128);

    {   // author scores: writes-src
        MS ms; ms.nsc = 1;
        ms.att[0] = att_src + 3 * 128; ms.out[0] = sa0;
        ms.att[1] = ms.att[0]; ms.out[1] = sa0;
        ms.att[2] = ms.att[0]; ms.out[2] = sa0;
        ms.att[3] = ms.att[0]; ms.out[3] = sa0;
        att_multi_k<<<(NA * 8 + 255) / 256, 256>>>(xa, ms, NA);
    }
    {   // paper scores: writes-dst, cites-src, cites-dst
        MS ms; ms.nsc = 3;
        ms.att[0] = att_dst + 3 * 128; ms.out[0] = sp0;
        ms.att[1] = att_src + 5 * 128; ms.out[1] = sp2;
        ms.att[2] = att_dst + 5 * 128; ms.out[2] = sp3;
        ms.att[3] = ms.att[0]; ms.out[3] = sp0;
        att_multi_k<<<(NP * 8 + 255) / 256, 256>>>(xp, ms, NP);
    }

    // edge type 0: writes
    cudaMemsetAsync(denom, 0, (size_t)NP * 8 * sizeof(float));
    edge_passA<<<(EE + 255) / 256, 256>>>(ei_w, sa0, sp0, escr, denom);
    cudaMemsetAsync(aggP0, 0, (size_t)NP * HID * sizeof(float));
    edge_passB<<<(EE * 32 + 255) / 256, 256>>>(ei_w, xa, escr, denom, aggP0);

    // edge type 2: cites
    cudaMemsetAsync(denom, 0, (size_t)NP * 8 * sizeof(float));
    edge_passA<<<(EE + 255) / 256, 256>>>(ei_c, sp2, sp3, escr, denom);
    cudaMemsetAsync(aggP1, 0, (size_t)NP * HID * sizeof(float));
    edge_passB<<<(EE * 32 + 255) / 256, 256>>>(ei_c, xp, escr, denom, aggP1);

    // semantic attention + fused final linear
    cudaMemsetAsync(colsum, 0, 2 * 128 * sizeof(float));
    sgemm_k<1, 1><<<(NP + 127) / 128, 256>>>(
        aggP0, klin_w + (size_t)128 * 128, klin_b + 128, nullptr, colsum, NP, 128);
    sgemm_k<1, 1><<<(NP + 127) / 128, 256>>>(
        aggP1, klin_w + (size_t)128 * 128, klin_b + 128, nullptr, colsum + 128, NP, 128);
    sem_attn_k<<<1, 128>>>(colsum, q + 128, attn);

    final_lin_k<<<(NP + 255) / 256, 256>>>(aggP0, aggP1, attn, lin_w, lin_b, out);
}

// round 9
// speedup vs baseline: 1.9610x; 1.0588x over previous
#include <cuda_runtime.h>
#include <cstddef>

#define NA 20000
#define NP 40000
#define EE 400000
#define HID 128
#define NCLS 16

// ----------------------------- scratch (static device globals) -------------------
__device__ float g_auth0[NA * HID];         // x_author @ Wa
__device__ float g_aggA[NA * HID];          // author aggregation (written_by, l0)
__device__ float g_pap[NP * HID];           // paper features after layer-0 combine
__device__ float g_xa[NA * HID];            // xh author
__device__ float g_xp[NP * HID];            // xh paper
__device__ float g_aggP0[NP * HID];
__device__ float g_aggP1[NP * HID];
__device__ float g_sa0[NA * 8];
__device__ float g_sa1[NA * 8];
__device__ float g_sp0[NP * 8];
__device__ float g_sp1[NP * 8];
__device__ float g_sp2[NP * 8];
__device__ float g_sp3[NP * 8];
__device__ float g_colsum[2 * HID];
__device__ float g_attn[2];
__device__ float g_zb[HID];                 // zero bias
// CSR (dst-indexed) adjacency, built once per launch, reused by both layers
__device__ int g_rp_w[NP + 1];              // writes:      dst = paper
__device__ int g_rp_wb[NA + 1];             // written_by:  dst = author
__device__ int g_rp_c[NP + 1];              // cites:       dst = paper
__device__ int g_src_w[EE];                 // source node ids, CSR order
__device__ int g_src_wb[EE];
__device__ int g_src_c[EE];
__device__ int g_cnt[NP];                   // histogram / scatter cursor (reused)

// ----------------------------- CSR build -----------------------------------------
__global__ void hist_k(const int* __restrict__ ei_dst, int* __restrict__ cnt)
{
    const int e = blockIdx.x * blockDim.x + threadIdx.x;
    if (e < EE) atomicAdd(&cnt[__ldg(&ei_dst[e])], 1);
}

// single-block inclusive scan -> rowptr (exclusive offsets), n <= 40000
__global__ void scan_k(const int* __restrict__ cnt, int* __restrict__ rowptr, int n)
{
    __shared__ int sdata[1024];
    __shared__ int carry;
    const int tid = threadIdx.x;
    if (tid == 0) { carry = 0; rowptr[0] = 0; }
    __syncthreads();
    for (int base = 0; base < n; base += 1024) {
        const int i = base + tid;
        sdata[tid] = (i < n) ? cnt[i] : 0;
        __syncthreads();
        for (int off = 1; off < 1024; off <<= 1) {
            int t = (tid >= off) ? sdata[tid - off] : 0;
            __syncthreads();
            sdata[tid] += t;
            __syncthreads();
        }
        if (i < n) rowptr[i + 1] = carry + sdata[tid];
        const int total = sdata[1023];
        __syncthreads();
        if (tid == 0) carry += total;
        __syncthreads();
    }
}

// scatter SOURCE ids into CSR slots (one indirection removed from hot loop)
__global__ void scatter_k(const int* __restrict__ ei, const int* __restrict__ rowptr,
                          int* __restrict__ cursor, int* __restrict__ srcs)
{
    const int e = blockIdx.x * blockDim.x + threadIdx.x;
    if (e >= EE) return;
    const int si = __ldg(&ei[e]);
    const int di = __ldg(&ei[EE + e]);
    const int pos = atomicAdd(&cursor[di], 1);
    srcs[rowptr[di] + pos] = si;
}

// ----------------------------- fused CSR aggregation ------------------------------
// One warp per dst node. agg[d] = Sum_e exp(lrelu(a_src[si]+a_dst[d])) * xh[si]
//                                 / Sum_e exp(...)        (per head)
// Linearity of softmax-weighted mean -> single pass, no escr, no denom, no atomics.
__global__ __launch_bounds__(256)
void agg_csr_k(const int* __restrict__ rowptr, const int* __restrict__ srcs,
               const float* __restrict__ asrc, const float* __restrict__ adst,
               const float* __restrict__ xh, float* __restrict__ agg, int ndst)
{
    const int w = (blockIdx.x * blockDim.x + threadIdx.x) >> 5;
    if (w >= ndst) return;
    const int lane = threadIdx.x & 31;
    const int h = lane >> 2;                       // head for this lane's 4 features
    const int start = __ldg(&rowptr[w]);
    const int end   = __ldg(&rowptr[w + 1]);
    const float ad = __ldg(&adst[(size_t)w * 8 + h]);

    float4 acc = make_float4(0.f, 0.f, 0.f, 0.f);
    float den = 0.f;
    for (int p = start; p < end; p++) {
        const int si = __ldg(&srcs[p]);
        float a = __ldg(&asrc[(size_t)si * 8 + h]) + ad;
        a = (a >= 0.f) ? a : 0.2f * a;             // leaky_relu
        const float e = __expf(a);
        den += e;
        float4 v = __ldg(((const float4*)xh) + (size_t)si * 32 + lane);
        acc.x = fmaf(e, v.x, acc.x);
        acc.y = fmaf(e, v.y, acc.y);
        acc.z = fmaf(e, v.z, acc.z);
        acc.w = fmaf(e, v.w, acc.w);
    }
    const float inv = 1.f / (den + 1e-16f);
    acc.x *= inv; acc.y *= inv; acc.z *= inv; acc.w *= inv;
    ((float4*)agg)[(size_t)w * 32 + lane] = acc;
}

// ----------------------------- SGEMM (R4-proven): C[Mx128]=(relu?)A[MxK]@B+bias ---
template <int TANH_COLSUM, int RELUA>
__global__ __launch_bounds__(256)
void sgemm_k(const float* __restrict__ A, const float* __restrict__ B,
             const float* __restrict__ bias, float* __restrict__ C,
             float* __restrict__ colsum, int M, int K)
{
    __shared__ alignas(16) float As[8][128];
    __shared__ alignas(16) float Bs[8][128];

    const int tid = threadIdx.x;
    const int tx = tid & 15;
    const int ty = tid >> 4;
    const int block_row = blockIdx.x * 128;

    const int a_row = tid >> 1;
    const int a_col = (tid & 1) * 4;
    const int b_row = tid >> 5;
    const int b_col = (tid & 31) * 4;

    float acc[8][8];
#pragma unroll
    for (int i = 0; i < 8; i++)
#pragma unroll
        for (int j = 0; j < 8; j++) acc[i][j] = 0.f;

    for (int k0 = 0; k0 < K; k0 += 8) {
        const int gr = block_row + a_row;
        float4 av = make_float4(0.f, 0.f, 0.f, 0.f);
        if (gr < M) av = *(const float4*)(A + (size_t)gr * K + k0 + a_col);
        if constexpr (RELUA) {
            av.x = fmaxf(av.x, 0.f); av.y = fmaxf(av.y, 0.f);
            av.z = fmaxf(av.z, 0.f); av.w = fmaxf(av.w, 0.f);
        }
        As[a_col + 0][a_row] = av.x;
        As[a_col + 1][a_row] = av.y;
        As[a_col + 2][a_row] = av.z;
        As[a_col + 3][a_row] = av.w;
        *(float4*)&Bs[b_row][b_col] =
            *(const float4*)(B + (size_t)(k0 + b_row) * 128 + b_col);
        __syncthreads();

#pragma unroll
        for (int k = 0; k < 8; k++) {
            float4 a0 = *(const float4*)&As[k][ty * 8];
            float4 a1 = *(const float4*)&As[k][ty * 8 + 4];
            float4 b0 = *(const float4*)&Bs[k][tx * 8];
            float4 b1 = *(const float4*)&Bs[k][tx * 8 + 4];
            float ar[8] = {a0.x, a0.y, a0.z, a0.w, a1.x, a1.y, a1.z, a1.w};
            float br[8] = {b0.x, b0.y, b0.z, b0.w, b1.x, b1.y, b1.z, b1.w};
#pragma unroll
            for (int i = 0; i < 8; i++)
#pragma unroll
                for (int j = 0; j < 8; j++)
                    acc[i][j] = fmaf(ar[i], br[j], acc[i][j]);
        }
        __syncthreads();
    }

    float bc[8];
#pragma unroll
    for (int j = 0; j < 8; j++) bc[j] = __ldg(&bias[tx * 8 + j]);

    if constexpr (TANH_COLSUM) {
        __shared__ float red[128];
        if (tid < 128) red[tid] = 0.f;
        __syncthreads();
        float cs[8];
#pragma unroll
        for (int j = 0; j < 8; j++) cs[j] = 0.f;
#pragma unroll
        for (int i = 0; i < 8; i++) {
            const int r = block_row + ty * 8 + i;
            if (r < M) {
#pragma unroll
                for (int j = 0; j < 8; j++)
                    cs[j] += tanhf(acc[i][j] + bc[j]);
            }
        }
#pragma unroll
        for (int j = 0; j < 8; j++) atomicAdd(&red[tx * 8 + j], cs[j]);
        __syncthreads();
        if (tid < 128) atomicAdd(&colsum[tid], red[tid]);
    } else {
#pragma unroll
        for (int i = 0; i < 8; i++) {
            const int r = block_row + ty * 8 + i;
            if (r < M) {
                float4 v0 = make_float4(acc[i][0] + bc[0], acc[i][1] + bc[1],
                                        acc[i][2] + bc[2], acc[i][3] + bc[3]);
                float4 v1 = make_float4(acc[i][4] + bc[4], acc[i][5] + bc[5],
                                        acc[i][6] + bc[6], acc[i][7] + bc[7]);
                *(float4*)(C + (size_t)r * 128 + tx * 8)     = v0;
                *(float4*)(C + (size_t)r * 128 + tx * 8 + 4) = v1;
            }
        }
    }
}

// ----------------------------- multi attention scores (1 xh pass, <=4 scores) -----
struct MS { const float* att[4]; float* out[4]; int nsc; };

__global__ void att_multi_k(const float* __restrict__ xh, MS ms, int N)
{
    const int t = blockIdx.x * blockDim.x + threadIdx.x;
    if (t >= N * 8) return;
    const int n = t >> 3, h = t & 7;
    const float4* xr = (const float4*)(xh + (size_t)n * HID + h * 16);
    float4 x0 = __ldg(&xr[0]), x1 = __ldg(&xr[1]);
    float4 x2 = __ldg(&xr[2]), x3 = __ldg(&xr[3]);
#pragma unroll
    for (int s = 0; s < 4; s++) {
        if (s < ms.nsc) {
            const float4* ar = (const float4*)(ms.att[s] + h * 16);
            float4 a0 = __ldg(&ar[0]), a1 = __ldg(&ar[1]);
            float4 a2 = __ldg(&ar[2]), a3 = __ldg(&ar[3]);
            float r = x0.x * a0.x + x0.y * a0.y + x0.z * a0.z + x0.w * a0.w
                    + x1.x * a1.x + x1.y * a1.y + x1.z * a1.z + x1.w * a1.w
                    + x2.x * a2.x + x2.y * a2.y + x2.z * a2.z + x2.w * a2.w
                    + x3.x * a3.x + x3.y * a3.y + x3.z * a3.z + x3.w * a3.w;
            ms.out[s][t] = r;
        }
    }
}

// ----------------------------- semantic attention weights (M=2) --------------------
__global__ void sem_attn_k(const float* __restrict__ colsum, const float* __restrict__ q,
                           float* __restrict__ attn)
{
    __shared__ float r0[128], r1[128];
    const int t = threadIdx.x;
    const float qv = q[t];
    r0[t] = qv * colsum[t];
    r1[t] = qv * colsum[128 + t];
    __syncthreads();
    for (int s = 64; s > 0; s >>= 1) {
        if (t < s) { r0[t] += r0[t + s]; r1[t] += r1[t + s]; }
        __syncthreads();
    }
    if (t == 0) {
        const float s0 = r0[0] / (float)NP;
        const float s1 = r1[0] / (float)NP;
        const float m = fmaxf(s0, s1);
        const float e0 = __expf(s0 - m), e1 = __expf(s1 - m);
        const float inv = 1.f / (e0 + e1);
        attn[0] = e0 * inv;
        attn[1] = e1 * inv;
    }
}

// ----------------------------- combine (layer-0): pap = a0*relu(s0)+a1*relu(s1) ----
__global__ void combine_k(float4* __restrict__ out, const float4* __restrict__ s0,
                          const float4* __restrict__ s1, const float* __restrict__ attn,
                          int n4)
{
    const int i = blockIdx.x * blockDim.x + threadIdx.x;
    if (i >= n4) return;
    const float a0 = __ldg(&attn[0]);
    const float a1 = __ldg(&attn[1]);
    float4 x = __ldg(&s0[i]);
    float4 y = __ldg(&s1[i]);
    x.x = fmaxf(x.x, 0.f); x.y = fmaxf(x.y, 0.f);
    x.z = fmaxf(x.z, 0.f); x.w = fmaxf(x.w, 0.f);
    y.x = fmaxf(y.x, 0.f); y.y = fmaxf(y.y, 0.f);
    y.z = fmaxf(y.z, 0.f); y.w = fmaxf(y.w, 0.f);
    out[i] = make_float4(a0 * x.x + a1 * y.x, a0 * x.y + a1 * y.y,
                         a0 * x.z + a1 * y.z, a0 * x.w + a1 * y.w);
}

// ----------------------------- final linear (fused layer-1 combine + relu) ---------
__global__ __launch_bounds__(256)
void final_lin_k(const float* __restrict__ s0, const float* __restrict__ s1,
                 const float* __restrict__ attn, const float* __restrict__ W,
                 const float* __restrict__ b, float* __restrict__ out)
{
    __shared__ float Ws[128 * NCLS];
    for (int i = threadIdx.x; i < 128 * NCLS; i += blockDim.x) Ws[i] = W[i];
    __syncthreads();
    const int n = blockIdx.x * blockDim.x + threadIdx.x;
    if (n >= NP) return;
    const float a0 = __ldg(&attn[0]);
    const float a1 = __ldg(&attn[1]);
    float acc[NCLS];
#pragma unroll
    for (int c = 0; c < NCLS; c++) acc[c] = __ldg(&b[c]);
    const float4* x0 = (const float4*)(s0 + (size_t)n * 128);
    const float4* x1 = (const float4*)(s1 + (size_t)n * 128);
#pragma unroll
    for (int k4 = 0; k4 < 32; k4++) {
        float4 u = __ldg(&x0[k4]);
        float4 v = __ldg(&x1[k4]);
        const float xs[4] = {
            a0 * fmaxf(u.x, 0.f) + a1 * fmaxf(v.x, 0.f),
            a0 * fmaxf(u.y, 0.f) + a1 * fmaxf(v.y, 0.f),
            a0 * fmaxf(u.z, 0.f) + a1 * fmaxf(v.z, 0.f),
            a0 * fmaxf(u.w, 0.f) + a1 * fmaxf(v.w, 0.f)};
#pragma unroll
        for (int uu = 0; uu < 4; uu++) {
            const int k = k4 * 4 + uu;
#pragma unroll
            for (int c = 0; c < NCLS; c++)
                acc[c] = fmaf(xs[uu], Ws[k * NCLS + c], acc[c]);
        }
    }
    float4* op = (float4*)(out + (size_t)n * NCLS);
#pragma unroll
    for (int c4 = 0; c4 < 4; c4++)
        op[c4] = make_float4(acc[c4 * 4], acc[c4 * 4 + 1], acc[c4 * 4 + 2], acc[c4 * 4 + 3]);
}

// ----------------------------- host orchestration ----------------------------------
extern "C" void kernel_launch(void* const* d_in, const int* in_sizes, int n_in,
                              void* d_out, int out_size)
{
    const float* x_author = (const float*)d_in[0];
    const float* x_paper  = (const float*)d_in[1];
    const float* Wa       = (const float*)d_in[2];
    const float* proj_w   = (const float*)d_in[3];
    const float* proj_b   = (const float*)d_in[4];
    const float* att_src  = (const float*)d_in[5];
    const float* att_dst  = (const float*)d_in[6];
    const float* klin_w   = (const float*)d_in[7];
    const float* klin_b   = (const float*)d_in[8];
    const float* q        = (const float*)d_in[9];
    const float* lin_w    = (const float*)d_in[10];
    const float* lin_b    = (const float*)d_in[11];
    const int*   ei_w     = (const int*)d_in[12];
    const int*   ei_wb    = (const int*)d_in[13];
    const int*   ei_c     = (const int*)d_in[14];
    float* out = (float*)d_out;

    float *auth0, *aggA, *pap, *xa, *xp, *aggP0, *aggP1;
    float *sa0, *sa1, *sp0, *sp1, *sp2, *sp3, *colsum, *attn, *zb;
    int *rp_w, *rp_wb, *rp_c, *src_w, *src_wb, *src_c, *cnt;
    cudaGetSymbolAddress((void**)&auth0, g_auth0);
    cudaGetSymbolAddress((void**)&aggA, g_aggA);
    cudaGetSymbolAddress((void**)&pap, g_pap);
    cudaGetSymbolAddress((void**)&xa, g_xa);
    cudaGetSymbolAddress((void**)&xp, g_xp);
    cudaGetSymbolAddress((void**)&aggP0, g_aggP0);
    cudaGetSymbolAddress((void**)&aggP1, g_aggP1);
    cudaGetSymbolAddress((void**)&sa0, g_sa0);
    cudaGetSymbolAddress((void**)&sa1, g_sa1);
    cudaGetSymbolAddress((void**)&sp0, g_sp0);
    cudaGetSymbolAddress((void**)&sp1, g_sp1);
    cudaGetSymbolAddress((void**)&sp2, g_sp2);
    cudaGetSymbolAddress((void**)&sp3, g_sp3);
    cudaGetSymbolAddress((void**)&colsum, g_colsum);
    cudaGetSymbolAddress((void**)&attn, g_attn);
    cudaGetSymbolAddress((void**)&zb, g_zb);
    cudaGetSymbolAddress((void**)&rp_w, g_rp_w);
    cudaGetSymbolAddress((void**)&rp_wb, g_rp_wb);
    cudaGetSymbolAddress((void**)&rp_c, g_rp_c);
    cudaGetSymbolAddress((void**)&src_w, g_src_w);
    cudaGetSymbolAddress((void**)&src_wb, g_src_wb);
    cudaGetSymbolAddress((void**)&src_c, g_src_c);
    cudaGetSymbolAddress((void**)&cnt, g_cnt);

    const int EB = (EE + 255) / 256;

    // ---- build dst-CSR for all 3 edge types (graph static across layers) ----
    cudaMemsetAsync(cnt, 0, NP * sizeof(int));
    hist_k<<<EB, 256>>>(ei_w + EE, cnt);
    scan_k<<<1, 1024>>>(cnt, rp_w, NP);
    cudaMemsetAsync(cnt, 0, NP * sizeof(int));
    scatter_k<<<EB, 256>>>(ei_w, rp_w, cnt, src_w);

    cudaMemsetAsync(cnt, 0, NA * sizeof(int));
    hist_k<<<EB, 256>>>(ei_wb + EE, cnt);
    scan_k<<<1, 1024>>>(cnt, rp_wb, NA);
    cudaMemsetAsync(cnt, 0, NA * sizeof(int));
    scatter_k<<<EB, 256>>>(ei_wb, rp_wb, cnt, src_wb);

    cudaMemsetAsync(cnt, 0, NP * sizeof(int));
    hist_k<<<EB, 256>>>(ei_c + EE, cnt);
    scan_k<<<1, 1024>>>(cnt, rp_c, NP);
    cudaMemsetAsync(cnt, 0, NP * sizeof(int));
    scatter_k<<<EB, 256>>>(ei_c, rp_c, cnt, src_c);

    // author raw projection: [20000,64] @ [64,128] (no bias)
    sgemm_k<0, 0><<<(NA + 127) / 128, 256>>>(x_author, Wa, zb, auth0, nullptr, NA, 64);

    // =============================== layer 0 ===============================
    sgemm_k<0, 0><<<(NA + 127) / 128, 256>>>(
        auth0, proj_w, proj_b, xa, nullptr, NA, 128);
    sgemm_k<0, 0><<<(NP + 127) / 128, 256>>>(
        x_paper, proj_w + (size_t)128 * 128, proj_b + 128, xp, nullptr, NP, 128);

    {   // author scores: writes-src, written_by-dst
        MS ms; ms.nsc = 2;
        ms.att[0] = att_src + 0 * 128; ms.out[0] = sa0;
        ms.att[1] = att_dst + 1 * 128; ms.out[1] = sa1;
        ms.att[2] = ms.att[0]; ms.out[2] = sa0; ms.att[3] = ms.att[0]; ms.out[3] = sa0;
        att_multi_k<<<(NA * 8 + 255) / 256, 256>>>(xa, ms, NA);
    }
    {   // paper scores: writes-dst, wb-src, cites-src, cites-dst
        MS ms; ms.nsc = 4;
        ms.att[0] = att_dst + 0 * 128; ms.out[0] = sp0;
        ms.att[1] = att_src + 1 * 128; ms.out[1] = sp1;
        ms.att[2] = att_src + 2 * 128; ms.out[2] = sp2;
        ms.att[3] = att_dst + 2 * 128; ms.out[3] = sp3;
        att_multi_k<<<(NP * 8 + 255) / 256, 256>>>(xp, ms, NP);
    }

    // fused single-pass aggregations (sequential: each WS stays L2-resident)
    agg_csr_k<<<(NP * 32 + 255) / 256, 256>>>(rp_w,  src_w,  sa0, sp0, xa, aggP0, NP);
    agg_csr_k<<<(NA * 32 + 255) / 256, 256>>>(rp_wb, src_wb, sp1, sa1, xp, aggA,  NA);
    agg_csr_k<<<(NP * 32 + 255) / 256, 256>>>(rp_c,  src_c,  sp2, sp3, xp, aggP1, NP);

    // semantic attention (relu fused into tanh-gemm A-load)
    cudaMemsetAsync(colsum, 0, 2 * 128 * sizeof(float));
    sgemm_k<1, 1><<<(NP + 127) / 128, 256>>>(
        aggP0, klin_w, klin_b, nullptr, colsum, NP, 128);
    sgemm_k<1, 1><<<(NP + 127) / 128, 256>>>(
        aggP1, klin_w, klin_b, nullptr, colsum + 128, NP, 128);
    sem_attn_k<<<1, 128>>>(colsum, q, attn);
    combine_k<<<(NP * 32 + 255) / 256, 256>>>(
        (float4*)pap, (const float4*)aggP0, (const float4*)aggP1, attn, NP * 32);

    // =============================== layer 1 ===============================
    // written_by chain dead at last layer (author output never read).
    sgemm_k<0, 1><<<(NA + 127) / 128, 256>>>(     // relu(aggA) fused into A-load
        aggA, proj_w + (size_t)2 * 128 * 128, proj_b + 2 * 128, xa, nullptr, NA, 128);
    sgemm_k<0, 0><<<(NP + 127) / 128, 256>>>(
        pap, proj_w + (size_t)3 * 128 * 128, proj_b + 3 * 128, xp, nullptr, NP, 128);

    {   // author scores: writes-src
        MS ms; ms.nsc = 1;
        ms.att[0] = att_src + 3 * 128; ms.out[0] = sa0;
        ms.att[1] = ms.att[0]; ms.out[1] = sa0;
        ms.att[2] = ms.att[0]; ms.out[2] = sa0;
        ms.att[3] = ms.att[0]; ms.out[3] = sa0;
        att_multi_k<<<(NA * 8 + 255) / 256, 256>>>(xa, ms, NA);
    }
    {   // paper scores: writes-dst, cites-src, cites-dst
        MS ms; ms.nsc = 3;
        ms.att[0] = att_dst + 3 * 128; ms.out[0] = sp0;
        ms.att[1] = att_src + 5 * 128; ms.out[1] = sp2;
        ms.att[2] = att_dst + 5 * 128; ms.out[2] = sp3;
        ms.att[3] = ms.att[0]; ms.out[3] = sp0;
        att_multi_k<<<(NP * 8 + 255) / 256, 256>>>(xp, ms, NP);
    }

    agg_csr_k<<<(NP * 32 + 255) / 256, 256>>>(rp_w, src_w, sa0, sp0, xa, aggP0, NP);
    agg_csr_k<<<(NP * 32 + 255) / 256, 256>>>(rp_c, src_c, sp2, sp3, xp, aggP1, NP);

    // semantic attention + fused final linear
    cudaMemsetAsync(colsum, 0, 2 * 128 * sizeof(float));
    sgemm_k<1, 1><<<(NP + 127) / 128, 256>>>(
        aggP0, klin_w + (size_t)128 * 128, klin_b + 128, nullptr, colsum, NP, 128);
    sgemm_k<1, 1><<<(NP + 127) / 128, 256>>>(
        aggP1, klin_w + (size_t)128 * 128, klin_b + 128, nullptr, colsum + 128, NP, 128);
    sem_attn_k<<<1, 128>>>(colsum, q + 128, attn);

    final_lin_k<<<(NP + 255) / 256, 256>>>(aggP0, aggP1, attn, lin_w, lin_b, out);
}

// round 10
// speedup vs baseline: 2.6957x; 1.3746x over previous
#include <cuda_runtime.h>
#include <cstddef>

#define NA 20000
#define NP 40000
#define EE 400000
#define HID 128
#define NCLS 16

// ----------------------------- scratch (static device globals) -------------------
__device__ float g_auth0[NA * HID];         // x_author @ Wa
__device__ float g_aggA[NA * HID];          // author aggregation (written_by, l0)
__device__ float g_xa[NA * HID];            // xh author
__device__ float g_xp[NP * HID];            // xh paper
__device__ float g_aggP0[NP * HID];
__device__ float g_aggP1[NP * HID];
__device__ float g_sa0[NA * 8];
__device__ float g_sa1[NA * 8];
__device__ float g_sp0[NP * 8];
__device__ float g_sp1[NP * 8];
__device__ float g_sp2[NP * 8];
__device__ float g_sp3[NP * 8];
__device__ float g_colsum[2 * HID];
__device__ float g_attn0[2];                // layer-0 semantic weights
__device__ float g_attn1[2];                // layer-1 semantic weights
__device__ float g_zb[HID];                 // zero bias
// CSR (dst-indexed) adjacency, built once per launch, reused by both layers
__device__ int g_rp_w[NP + 1];
__device__ int g_rp_wb[NA + 1];
__device__ int g_rp_c[NP + 1];
__device__ int g_src_w[EE];
__device__ int g_src_wb[EE];
__device__ int g_src_c[EE];
__device__ int g_cnt[NP + NA + NP];         // per-type histograms / cursors
__device__ int g_aux[3 * 256];              // per-type block-sum aux for scan

// ----------------------------- CSR build (full-chip, 3-phase scan) ----------------
struct H3 { const int* dst[3]; int* cnt[3]; };
__global__ void hist3_k(H3 p)
{
    const int y = blockIdx.y;
    const int e = blockIdx.x * blockDim.x + threadIdx.x;
    if (e < EE) atomicAdd(&p.cnt[y][__ldg(&p.dst[y][e])], 1);
}

// phase 1: per-256-block inclusive scan; rowptr[i+1] = local inclusive; aux[b]=total
__global__ void scan_blk_k(const int* __restrict__ cnt, int* __restrict__ rowptr,
                           int* __restrict__ aux, int n)
{
    __shared__ int s[256];
    const int tid = threadIdx.x;
    const int i = blockIdx.x * 256 + tid;
    s[tid] = (i < n) ? cnt[i] : 0;
    __syncthreads();
#pragma unroll
    for (int off = 1; off < 256; off <<= 1) {
        int t = (tid >= off) ? s[tid - off] : 0;
        __syncthreads();
        s[tid] += t;
        __syncthreads();
    }
    if (i < n) rowptr[i + 1] = s[tid];
    if (tid == 255) aux[blockIdx.x] = s[255];
}

// phase 2: single block exclusive scan of aux (nb <= 256)
__global__ void scan_aux_k(int* __restrict__ aux, int nb)
{
    __shared__ int s[256];
    const int tid = threadIdx.x;
    int v = (tid < nb) ? aux[tid] : 0;
    s[tid] = v;
    __syncthreads();
#pragma unroll
    for (int off = 1; off < 256; off <<= 1) {
        int t = (tid >= off) ? s[tid - off] : 0;
        __syncthreads();
        s[tid] += t;
        __syncthreads();
    }
    if (tid < nb) aux[tid] = s[tid] - v;   // exclusive
}

// phase 3: add block offsets
__global__ void scan_add_k(int* __restrict__ rowptr, const int* __restrict__ aux, int n)
{
    const int i = blockIdx.x * blockDim.x + threadIdx.x;
    if (i < n) rowptr[i + 1] += aux[i >> 8];
    if (i == 0) rowptr[0] = 0;
}

struct S3 { const int* ei[3]; const int* rowptr[3]; int* cursor[3]; int* srcs[3]; };
__global__ void scatter3_k(S3 p)
{
    const int y = blockIdx.y;
    const int e = blockIdx.x * blockDim.x + threadIdx.x;
    if (e >= EE) return;
    const int si = __ldg(&p.ei[y][e]);
    const int di = __ldg(&p.ei[y][EE + e]);
    const int pos = atomicAdd(&p.cursor[y][di], 1);
    p.srcs[y][p.rowptr[y][di] + pos] = si;
}

// ----------------------------- fused CSR aggregation (R8-proven) -------------------
__global__ __launch_bounds__(256)
void agg_csr_k(const int* __restrict__ rowptr, const int* __restrict__ srcs,
               const float* __restrict__ asrc, const float* __restrict__ adst,
               const float* __restrict__ xh, float* __restrict__ agg, int ndst)
{
    const int w = (blockIdx.x * blockDim.x + threadIdx.x) >> 5;
    if (w >= ndst) return;
    const int lane = threadIdx.x & 31;
    const int h = lane >> 2;
    const int start = __ldg(&rowptr[w]);
    const int end   = __ldg(&rowptr[w + 1]);
    const float ad = __ldg(&adst[(size_t)w * 8 + h]);

    float4 acc = make_float4(0.f, 0.f, 0.f, 0.f);
    float den = 0.f;
    for (int p = start; p < end; p++) {
        const int si = __ldg(&srcs[p]);
        float a = __ldg(&asrc[(size_t)si * 8 + h]) + ad;
        a = (a >= 0.f) ? a : 0.2f * a;
        const float e = __expf(a);
        den += e;
        float4 v = __ldg(((const float4*)xh) + (size_t)si * 32 + lane);
        acc.x = fmaf(e, v.x, acc.x);
        acc.y = fmaf(e, v.y, acc.y);
        acc.z = fmaf(e, v.z, acc.z);
        acc.w = fmaf(e, v.w, acc.w);
    }
    const float inv = 1.f / (den + 1e-16f);
    acc.x *= inv; acc.y *= inv; acc.z *= inv; acc.w *= inv;
    ((float4*)agg)[(size_t)w * 32 + lane] = acc;
}

// ----------------------------- SGEMM, software-pipelined ---------------------------
// C[Mx128] = f(A) @ B[Kx128] + bias,   f per template:
//   RELUA:   f = relu(A0)
//   COMBINE: f = attn[0]*relu(A0) + attn[1]*relu(A1)
//   TANH:    A = blockIdx.y ? A1 : A0 (+relu); skip C; colsum[y*128+c] += sum tanh
template <int TANH, int RELUA, int COMBINE>
__global__ __launch_bounds__(256)
void sgemm_k(const float* __restrict__ A0, const float* __restrict__ A1,
             const float* __restrict__ attnp,
             const float* __restrict__ B, const float* __restrict__ bias,
             float* __restrict__ C, float* __restrict__ colsum, int M, int K)
{
    __shared__ alignas(16) float As[8][128];
    __shared__ alignas(16) float Bs[8][128];

    const float* A = (TANH && blockIdx.y) ? A1 : A0;
    float* cs = TANH ? colsum + blockIdx.y * 128 : colsum;

    const int tid = threadIdx.x;
    const int tx = tid & 15;
    const int ty = tid >> 4;
    const int block_row = blockIdx.x * 128;

    const int a_row = tid >> 1;
    const int a_col = (tid & 1) * 4;
    const int b_row = tid >> 5;
    const int b_col = (tid & 31) * 4;

    float ca0 = 0.f, ca1 = 0.f;
    if constexpr (COMBINE) { ca0 = __ldg(&attnp[0]); ca1 = __ldg(&attnp[1]); }

    const int gr = block_row + a_row;
    const bool arow_ok = (gr < M);

    float acc[8][8];
#pragma unroll
    for (int i = 0; i < 8; i++)
#pragma unroll
        for (int j = 0; j < 8; j++) acc[i][j] = 0.f;

    // register-staged tile (software pipeline: load k0+8 during compute of k0)
    float4 av, bv;
    {
        av = make_float4(0.f, 0.f, 0.f, 0.f);
        if (arow_ok) {
            av = *(const float4*)(A + (size_t)gr * K + a_col);
            if constexpr (COMBINE) {
                float4 w2 = *(const float4*)(A1 + (size_t)gr * K + a_col);
                av.x = ca0 * fmaxf(av.x, 0.f) + ca1 * fmaxf(w2.x, 0.f);
                av.y = ca0 * fmaxf(av.y, 0.f) + ca1 * fmaxf(w2.y, 0.f);
                av.z = ca0 * fmaxf(av.z, 0.f) + ca1 * fmaxf(w2.z, 0.f);
                av.w = ca0 * fmaxf(av.w, 0.f) + ca1 * fmaxf(w2.w, 0.f);
            } else if constexpr (RELUA || TANH) {
                av.x = fmaxf(av.x, 0.f); av.y = fmaxf(av.y, 0.f);
                av.z = fmaxf(av.z, 0.f); av.w = fmaxf(av.w, 0.f);
            }
        }
        bv = *(const float4*)(B + (size_t)b_row * 128 + b_col);
    }

    for (int k0 = 0; k0 < K; k0 += 8) {
        As[a_col + 0][a_row] = av.x;
        As[a_col + 1][a_row] = av.y;
        As[a_col + 2][a_row] = av.z;
        As[a_col + 3][a_row] = av.w;
        *(float4*)&Bs[b_row][b_col] = bv;
        __syncthreads();

        if (k0 + 8 < K) {   // prefetch next tile into regs (overlaps FFMA below)
            av = make_float4(0.f, 0.f, 0.f, 0.f);
            if (arow_ok) {
                av = *(const float4*)(A + (size_t)gr * K + k0 + 8 + a_col);
                if constexpr (COMBINE) {
                    float4 w2 = *(const float4*)(A1 + (size_t)gr * K + k0 + 8 + a_col);
                    av.x = ca0 * fmaxf(av.x, 0.f) + ca1 * fmaxf(w2.x, 0.f);
                    av.y = ca0 * fmaxf(av.y, 0.f) + ca1 * fmaxf(w2.y, 0.f);
                    av.z = ca0 * fmaxf(av.z, 0.f) + ca1 * fmaxf(w2.z, 0.f);
                    av.w = ca0 * fmaxf(av.w, 0.f) + ca1 * fmaxf(w2.w, 0.f);
                } else if constexpr (RELUA || TANH) {
                    av.x = fmaxf(av.x, 0.f); av.y = fmaxf(av.y, 0.f);
                    av.z = fmaxf(av.z, 0.f); av.w = fmaxf(av.w, 0.f);
                }
            }
            bv = *(const float4*)(B + (size_t)(k0 + 8 + b_row) * 128 + b_col);
        }

#pragma unroll
        for (int k = 0; k < 8; k++) {
            float4 a0 = *(const float4*)&As[k][ty * 8];
            float4 a1 = *(const float4*)&As[k][ty * 8 + 4];
            float4 b0 = *(const float4*)&Bs[k][tx * 8];
            float4 b1 = *(const float4*)&Bs[k][tx * 8 + 4];
            float ar[8] = {a0.x, a0.y, a0.z, a0.w, a1.x, a1.y, a1.z, a1.w};
            float br[8] = {b0.x, b0.y, b0.z, b0.w, b1.x, b1.y, b1.z, b1.w};
#pragma unroll
            for (int i = 0; i < 8; i++)
#pragma unroll
                for (int j = 0; j < 8; j++)
                    acc[i][j] = fmaf(ar[i], br[j], acc[i][j]);
        }
        __syncthreads();
    }

    float bc[8];
#pragma unroll
    for (int j = 0; j < 8; j++) bc[j] = __ldg(&bias[tx * 8 + j]);

    if constexpr (TANH) {
        __shared__ float red[128];
        if (tid < 128) red[tid] = 0.f;
        __syncthreads();
        float csr[8];
#pragma unroll
        for (int j = 0; j < 8; j++) csr[j] = 0.f;
#pragma unroll
        for (int i = 0; i < 8; i++) {
            const int r = block_row + ty * 8 + i;
            if (r < M) {
#pragma unroll
                for (int j = 0; j < 8; j++)
                    csr[j] += tanhf(acc[i][j] + bc[j]);
            }
        }
#pragma unroll
        for (int j = 0; j < 8; j++) atomicAdd(&red[tx * 8 + j], csr[j]);
        __syncthreads();
        if (tid < 128) atomicAdd(&cs[tid], red[tid]);
    } else {
#pragma unroll
        for (int i = 0; i < 8; i++) {
            const int r = block_row + ty * 8 + i;
            if (r < M) {
                float4 v0 = make_float4(acc[i][0] + bc[0], acc[i][1] + bc[1],
                                        acc[i][2] + bc[2], acc[i][3] + bc[3]);
                float4 v1 = make_float4(acc[i][4] + bc[4], acc[i][5] + bc[5],
                                        acc[i][6] + bc[6], acc[i][7] + bc[7]);
                *(float4*)(C + (size_t)r * 128 + tx * 8)     = v0;
                *(float4*)(C + (size_t)r * 128 + tx * 8 + 4) = v1;
            }
        }
    }
}

// ----------------------------- multi attention scores (R8-proven) ------------------
struct MS { const float* att[4]; float* out[4]; int nsc; };

__global__ void att_multi_k(const float* __restrict__ xh, MS ms, int N)
{
    const int t = blockIdx.x * blockDim.x + threadIdx.x;
    if (t >= N * 8) return;
    const int n = t >> 3, h = t & 7;
    const float4* xr = (const float4*)(xh + (size_t)n * HID + h * 16);
    float4 x0 = __ldg(&xr[0]), x1 = __ldg(&xr[1]);
    float4 x2 = __ldg(&xr[2]), x3 = __ldg(&xr[3]);
#pragma unroll
    for (int s = 0; s < 4; s++) {
        if (s < ms.nsc) {
            const float4* ar = (const float4*)(ms.att[s] + h * 16);
            float4 a0 = __ldg(&ar[0]), a1 = __ldg(&ar[1]);
            float4 a2 = __ldg(&ar[2]), a3 = __ldg(&ar[3]);
            float r = x0.x * a0.x + x0.y * a0.y + x0.z * a0.z + x0.w * a0.w
                    + x1.x * a1.x + x1.y * a1.y + x1.z * a1.z + x1.w * a1.w
                    + x2.x * a2.x + x2.y * a2.y + x2.z * a2.z + x2.w * a2.w
                    + x3.x * a3.x + x3.y * a3.y + x3.z * a3.z + x3.w * a3.w;
            ms.out[s][t] = r;
        }
    }
}

// ----------------------------- semantic attention weights (M=2) --------------------
__global__ void sem_attn_k(const float* __restrict__ colsum, const float* __restrict__ q,
                           float* __restrict__ attn)
{
    __shared__ float r0[128], r1[128];
    const int t = threadIdx.x;
    const float qv = q[t];
    r0[t] = qv * colsum[t];
    r1[t] = qv * colsum[128 + t];
    __syncthreads();
    for (int s = 64; s > 0; s >>= 1) {
        if (t < s) { r0[t] += r0[t + s]; r1[t] += r1[t + s]; }
        __syncthreads();
    }
    if (t == 0) {
        const float s0 = r0[0] / (float)NP;
        const float s1 = r1[0] / (float)NP;
        const float m = fmaxf(s0, s1);
        const float e0 = __expf(s0 - m), e1 = __expf(s1 - m);
        const float inv = 1.f / (e0 + e1);
        attn[0] = e0 * inv;
        attn[1] = e1 * inv;
    }
}

// ----------------------------- final linear (fused layer-1 combine + relu) ---------
__global__ __launch_bounds__(256)
void final_lin_k(const float* __restrict__ s0, const float* __restrict__ s1,
                 const float* __restrict__ attn, const float* __restrict__ W,
                 const float* __restrict__ b, float* __restrict__ out)
{
    __shared__ float Ws[128 * NCLS];
    for (int i = threadIdx.x; i < 128 * NCLS; i += blockDim.x) Ws[i] = W[i];
    __syncthreads();
    const int n = blockIdx.x * blockDim.x + threadIdx.x;
    if (n >= NP) return;
    const float a0 = __ldg(&attn[0]);
    const float a1 = __ldg(&attn[1]);
    float acc[NCLS];
#pragma unroll
    for (int c = 0; c < NCLS; c++) acc[c] = __ldg(&b[c]);
    const float4* x0 = (const float4*)(s0 + (size_t)n * 128);
    const float4* x1 = (const float4*)(s1 + (size_t)n * 128);
#pragma unroll
    for (int k4 = 0; k4 < 32; k4++) {
        float4 u = __ldg(&x0[k4]);
        float4 v = __ldg(&x1[k4]);
        const float xs[4] = {
            a0 * fmaxf(u.x, 0.f) + a1 * fmaxf(v.x, 0.f),
            a0 * fmaxf(u.y, 0.f) + a1 * fmaxf(v.y, 0.f),
            a0 * fmaxf(u.z, 0.f) + a1 * fmaxf(v.z, 0.f),
            a0 * fmaxf(u.w, 0.f) + a1 * fmaxf(v.w, 0.f)};
#pragma unroll
        for (int uu = 0; uu < 4; uu++) {
            const int k = k4 * 4 + uu;
#pragma unroll
            for (int c = 0; c < NCLS; c++)
                acc[c] = fmaf(xs[uu], Ws[k * NCLS + c], acc[c]);
        }
    }
    float4* op = (float4*)(out + (size_t)n * NCLS);
#pragma unroll
    for (int c4 = 0; c4 < 4; c4++)
        op[c4] = make_float4(acc[c4 * 4], acc[c4 * 4 + 1], acc[c4 * 4 + 2], acc[c4 * 4 + 3]);
}

// ----------------------------- host orchestration ----------------------------------
extern "C" void kernel_launch(void* const* d_in, const int* in_sizes, int n_in,
                              void* d_out, int out_size)
{
    const float* x_author = (const float*)d_in[0];
    const float* x_paper  = (const float*)d_in[1];
    const float* Wa       = (const float*)d_in[2];
    const float* proj_w   = (const float*)d_in[3];
    const float* proj_b   = (const float*)d_in[4];
    const float* att_src  = (const float*)d_in[5];
    const float* att_dst  = (const float*)d_in[6];
    const float* klin_w   = (const float*)d_in[7];
    const float* klin_b   = (const float*)d_in[8];
    const float* q        = (const float*)d_in[9];
    const float* lin_w    = (const float*)d_in[10];
    const float* lin_b    = (const float*)d_in[11];
    const int*   ei_w     = (const int*)d_in[12];
    const int*   ei_wb    = (const int*)d_in[13];
    const int*   ei_c     = (const int*)d_in[14];
    float* out = (float*)d_out;

    float *auth0, *aggA, *xa, *xp, *aggP0, *aggP1;
    float *sa0, *sa1, *sp0, *sp1, *sp2, *sp3, *colsum, *attn0, *attn1, *zb;
    int *rp_w, *rp_wb, *rp_c, *src_w, *src_wb, *src_c, *cnt, *aux;
    cudaGetSymbolAddress((void**)&auth0, g_auth0);
    cudaGetSymbolAddress((void**)&aggA, g_aggA);
    cudaGetSymbolAddress((void**)&xa, g_xa);
    cudaGetSymbolAddress((void**)&xp, g_xp);
    cudaGetSymbolAddress((void**)&aggP0, g_aggP0);
    cudaGetSymbolAddress((void**)&aggP1, g_aggP1);
    cudaGetSymbolAddress((void**)&sa0, g_sa0);
    cudaGetSymbolAddress((void**)&sa1, g_sa1);
    cudaGetSymbolAddress((void**)&sp0, g_sp0);
    cudaGetSymbolAddress((void**)&sp1, g_sp1);
    cudaGetSymbolAddress((void**)&sp2, g_sp2);
    cudaGetSymbolAddress((void**)&sp3, g_sp3);
    cudaGetSymbolAddress((void**)&colsum, g_colsum);
    cudaGetSymbolAddress((void**)&attn0, g_attn0);
    cudaGetSymbolAddress((void**)&attn1, g_attn1);
    cudaGetSymbolAddress((void**)&zb, g_zb);
    cudaGetSymbolAddress((void**)&rp_w, g_rp_w);
    cudaGetSymbolAddress((void**)&rp_wb, g_rp_wb);
    cudaGetSymbolAddress((void**)&rp_c, g_rp_c);
    cudaGetSymbolAddress((void**)&src_w, g_src_w);
    cudaGetSymbolAddress((void**)&src_wb, g_src_wb);
    cudaGetSymbolAddress((void**)&src_c, g_src_c);
    cudaGetSymbolAddress((void**)&cnt, g_cnt);
    cudaGetSymbolAddress((void**)&aux, g_aux);

    int* cnt_w  = cnt;
    int* cnt_wb = cnt + NP;
    int* cnt_c  = cnt + NP + NA;
    int* aux_w  = aux;
    int* aux_wb = aux + 256;
    int* aux_c  = aux + 512;

    const int EB = (EE + 255) / 256;
    const int BW  = (NP + 255) / 256;   // 157
    const int BWB = (NA + 255) / 256;   // 79

    // ---- CSR build: merged histograms, full-chip 3-phase scans, merged scatter ----
    cudaMemsetAsync(cnt, 0, (2 * NP + NA) * sizeof(int));
    {
        H3 h; h.dst[0] = ei_w + EE; h.dst[1] = ei_wb + EE; h.dst[2] = ei_c + EE;
        h.cnt[0] = cnt_w; h.cnt[1] = cnt_wb; h.cnt[2] = cnt_c;
        hist3_k<<<dim3(EB, 3), 256>>>(h);
    }
    scan_blk_k<<<BW, 256>>>(cnt_w, rp_w, aux_w, NP);
    scan_blk_k<<<BWB, 256>>>(cnt_wb, rp_wb, aux_wb, NA);
    scan_blk_k<<<BW, 256>>>(cnt_c, rp_c, aux_c, NP);
    scan_aux_k<<<1, 256>>>(aux_w, BW);
    scan_aux_k<<<1, 256>>>(aux_wb, BWB);
    scan_aux_k<<<1, 256>>>(aux_c, BW);
    scan_add_k<<<BW, 256>>>(rp_w, aux_w, NP);
    scan_add_k<<<BWB, 256>>>(rp_wb, aux_wb, NA);
    scan_add_k<<<BW, 256>>>(rp_c, aux_c, NP);
    cudaMemsetAsync(cnt, 0, (2 * NP + NA) * sizeof(int));
    {
        S3 s;
        s.ei[0] = ei_w;  s.rowptr[0] = rp_w;  s.cursor[0] = cnt_w;  s.srcs[0] = src_w;
        s.ei[1] = ei_wb; s.rowptr[1] = rp_wb; s.cursor[1] = cnt_wb; s.srcs[1] = src_wb;
        s.ei[2] = ei_c;  s.rowptr[2] = rp_c;  s.cursor[2] = cnt_c;  s.srcs[2] = src_c;
        scatter3_k<<<dim3(EB, 3), 256>>>(s);
    }

    // author raw projection: [20000,64] @ [64,128] (no bias)
    sgemm_k<0, 0, 0><<<(NA + 127) / 128, 256>>>(
        x_author, nullptr, nullptr, Wa, zb, auth0, nullptr, NA, 64);

    // =============================== layer 0 ===============================
    sgemm_k<0, 0, 0><<<(NA + 127) / 128, 256>>>(
        auth0, nullptr, nullptr, proj_w, proj_b, xa, nullptr, NA, 128);
    sgemm_k<0, 0, 0><<<(NP + 127) / 128, 256>>>(
        x_paper, nullptr, nullptr, proj_w + (size_t)128 * 128, proj_b + 128,
        xp, nullptr, NP, 128);

    {   // author scores: writes-src, written_by-dst
        MS ms; ms.nsc = 2;
        ms.att[0] = att_src + 0 * 128; ms.out[0] = sa0;
        ms.att[1] = att_dst + 1 * 128; ms.out[1] = sa1;
        ms.att[2] = ms.att[0]; ms.out[2] = sa0; ms.att[3] = ms.att[0]; ms.out[3] = sa0;
        att_multi_k<<<(NA * 8 + 255) / 256, 256>>>(xa, ms, NA);
    }
    {   // paper scores: writes-dst, wb-src, cites-src, cites-dst
        MS ms; ms.nsc = 4;
        ms.att[0] = att_dst + 0 * 128; ms.out[0] = sp0;
        ms.att[1] = att_src + 1 * 128; ms.out[1] = sp1;
        ms.att[2] = att_src + 2 * 128; ms.out[2] = sp2;
        ms.att[3] = att_dst + 2 * 128; ms.out[3] = sp3;
        att_multi_k<<<(NP * 8 + 255) / 256, 256>>>(xp, ms, NP);
    }

    // fused single-pass aggregations (sequential: L2-resident working sets)
    agg_csr_k<<<(NP * 32 + 255) / 256, 256>>>(rp_w,  src_w,  sa0, sp0, xa, aggP0, NP);
    agg_csr_k<<<(NA * 32 + 255) / 256, 256>>>(rp_wb, src_wb, sp1, sa1, xp, aggA,  NA);
    agg_csr_k<<<(NP * 32 + 255) / 256, 256>>>(rp_c,  src_c,  sp2, sp3, xp, aggP1, NP);

    // semantic attention: merged tanh pair via grid.y (relu fused in A-load)
    cudaMemsetAsync(colsum, 0, 2 * 128 * sizeof(float));
    sgemm_k<1, 1, 0><<<dim3((NP + 127) / 128, 2), 256>>>(
        aggP0, aggP1, nullptr, klin_w, klin_b, nullptr, colsum, NP, 128);
    sem_attn_k<<<1, 128>>>(colsum, q, attn0);

    // =============================== layer 1 ===============================
    // written_by chain dead at last layer; layer-0 combine fused into A-load here.
    sgemm_k<0, 1, 0><<<(NA + 127) / 128, 256>>>(
        aggA, nullptr, nullptr, proj_w + (size_t)2 * 128 * 128, proj_b + 2 * 128,
        xa, nullptr, NA, 128);
    sgemm_k<0, 0, 1><<<(NP + 127) / 128, 256>>>(   // COMBINE: attn0-weighted relu sum
        aggP0, aggP1, attn0, proj_w + (size_t)3 * 128 * 128, proj_b + 3 * 128,
        xp, nullptr, NP, 128);

    {   // author scores: writes-src
        MS ms; ms.nsc = 1;
        ms.att[0] = att_src + 3 * 128; ms.out[0] = sa0;
        ms.att[1] = ms.att[0]; ms.out[1] = sa0;
        ms.att[2] = ms.att[0]; ms.out[2] = sa0;
        ms.att[3] = ms.att[0]; ms.out[3] = sa0;
        att_multi_k<<<(NA * 8 + 255) / 256, 256>>>(xa, ms, NA);
    }
    {   // paper scores: writes-dst, cites-src, cites-dst
        MS ms; ms.nsc = 3;
        ms.att[0] = att_dst + 3 * 128; ms.out[0] = sp0;
        ms.att[1] = att_src + 5 * 128; ms.out[1] = sp2;
        ms.att[2] = att_dst + 5 * 128; ms.out[2] = sp3;
        ms.att[3] = ms.att[0]; ms.out[3] = sp0;
        att_multi_k<<<(NP * 8 + 255) / 256, 256>>>(xp, ms, NP);
    }

    agg_csr_k<<<(NP * 32 + 255) / 256, 256>>>(rp_w, src_w, sa0, sp0, xa, aggP0, NP);
    agg_csr_k<<<(NP * 32 + 255) / 256, 256>>>(rp_c, src_c, sp2, sp3, xp, aggP1, NP);

    // semantic attention + fused final linear
    cudaMemsetAsync(colsum, 0, 2 * 128 * sizeof(float));
    sgemm_k<1, 1, 0><<<dim3((NP + 127) / 128, 2), 256>>>(
        aggP0, aggP1, nullptr, klin_w + (size_t)128 * 128, klin_b + 128,
        nullptr, colsum, NP, 128);
    sem_attn_k<<<1, 128>>>(colsum, q + 128, attn1);

    final_lin_k<<<(NP + 255) / 256, 256>>>(aggP0, aggP1, attn1, lin_w, lin_b, out);
}

// round 11
// speedup vs baseline: 3.2881x; 1.2198x over previous
#include <cuda_runtime.h>
#include <cstddef>

#define NA 20000
#define NP 40000
#define EE 400000
#define HID 128
#define NCLS 16

// ----------------------------- scratch (static device globals) -------------------
__device__ float g_auth0[NA * HID];
__device__ float g_aggA[NA * HID];
__device__ float g_xa[NA * HID];
__device__ float g_xp[NP * HID];
__device__ float g_aggP0[NP * HID];
__device__ float g_aggP1[NP * HID];
__device__ float g_sa0[NA * 8];
__device__ float g_sa1[NA * 8];
__device__ float g_sp0[NP * 8];
__device__ float g_sp1[NP * 8];
__device__ float g_sp2[NP * 8];
__device__ float g_sp3[NP * 8];
__device__ float g_colsum[2 * HID];
__device__ float g_attn0[2];
__device__ float g_attn1[2];
__device__ float g_zb[HID];
__device__ int g_rp_w[NP + 1];
__device__ int g_rp_wb[NA + 1];
__device__ int g_rp_c[NP + 1];
__device__ int g_src_w[EE];
__device__ int g_src_wb[EE];
__device__ int g_src_c[EE];
__device__ int g_cnt[NP + NA + NP];
__device__ int g_aux[3 * 256];

// ----------------------------- CSR build (R9-proven) ------------------------------
struct H3 { const int* dst[3]; int* cnt[3]; };
__global__ void hist3_k(H3 p)
{
    const int y = blockIdx.y;
    const int e = blockIdx.x * blockDim.x + threadIdx.x;
    if (e < EE) atomicAdd(&p.cnt[y][__ldg(&p.dst[y][e])], 1);
}

__global__ void scan_blk_k(const int* __restrict__ cnt, int* __restrict__ rowptr,
                           int* __restrict__ aux, int n)
{
    __shared__ int s[256];
    const int tid = threadIdx.x;
    const int i = blockIdx.x * 256 + tid;
    s[tid] = (i < n) ? cnt[i] : 0;
    __syncthreads();
#pragma unroll
    for (int off = 1; off < 256; off <<= 1) {
        int t = (tid >= off) ? s[tid - off] : 0;
        __syncthreads();
        s[tid] += t;
        __syncthreads();
    }
    if (i < n) rowptr[i + 1] = s[tid];
    if (tid == 255) aux[blockIdx.x] = s[255];
}

__global__ void scan_aux_k(int* __restrict__ aux, int nb)
{
    __shared__ int s[256];
    const int tid = threadIdx.x;
    int v = (tid < nb) ? aux[tid] : 0;
    s[tid] = v;
    __syncthreads();
#pragma unroll
    for (int off = 1; off < 256; off <<= 1) {
        int t = (tid >= off) ? s[tid - off] : 0;
        __syncthreads();
        s[tid] += t;
        __syncthreads();
    }
    if (tid < nb) aux[tid] = s[tid] - v;
}

__global__ void scan_add_k(int* __restrict__ rowptr, const int* __restrict__ aux, int n)
{
    const int i = blockIdx.x * blockDim.x + threadIdx.x;
    if (i < n) rowptr[i + 1] += aux[i >> 8];
    if (i == 0) rowptr[0] = 0;
}

struct S3 { const int* ei[3]; const int* rowptr[3]; int* cursor[3]; int* srcs[3]; };
__global__ void scatter3_k(S3 p)
{
    const int y = blockIdx.y;
    const int e = blockIdx.x * blockDim.x + threadIdx.x;
    if (e >= EE) return;
    const int si = __ldg(&p.ei[y][e]);
    const int di = __ldg(&p.ei[y][EE + e]);
    const int pos = atomicAdd(&p.cursor[y][di], 1);
    p.srcs[y][p.rowptr[y][di] + pos] = si;
}

// ----------------------------- fused CSR aggregation (R8-proven) -------------------
__global__ __launch_bounds__(256)
void agg_csr_k(const int* __restrict__ rowptr, const int* __restrict__ srcs,
               const float* __restrict__ asrc, const float* __restrict__ adst,
               const float* __restrict__ xh, float* __restrict__ agg, int ndst)
{
    const int w = (blockIdx.x * blockDim.x + threadIdx.x) >> 5;
    if (w >= ndst) return;
    const int lane = threadIdx.x & 31;
    const int h = lane >> 2;
    const int start = __ldg(&rowptr[w]);
    const int end   = __ldg(&rowptr[w + 1]);
    const float ad = __ldg(&adst[(size_t)w * 8 + h]);

    float4 acc = make_float4(0.f, 0.f, 0.f, 0.f);
    float den = 0.f;
    for (int p = start; p < end; p++) {
        const int si = __ldg(&srcs[p]);
        float a = __ldg(&asrc[(size_t)si * 8 + h]) + ad;
        a = (a >= 0.f) ? a : 0.2f * a;
        const float e = __expf(a);
        den += e;
        float4 v = __ldg(((const float4*)xh) + (size_t)si * 32 + lane);
        acc.x = fmaf(e, v.x, acc.x);
        acc.y = fmaf(e, v.y, acc.y);
        acc.z = fmaf(e, v.z, acc.z);
        acc.w = fmaf(e, v.w, acc.w);
    }
    const float inv = 1.f / (den + 1e-16f);
    acc.x *= inv; acc.y *= inv; acc.z *= inv; acc.w *= inv;
    ((float4*)agg)[(size_t)w * 32 + lane] = acc;
}

// ----------------------------- tf32 mma helpers ------------------------------------
__device__ __forceinline__ unsigned f2tf(float f) {
    unsigned u;
    asm("cvt.rna.tf32.f32 %0, %1;" : "=r"(u) : "f"(f));
    return u;
}
__device__ __forceinline__ float tfbits(float f) {
    return __uint_as_float(f2tf(f));
}
__device__ __forceinline__ void mma_tf32(float4& d, const unsigned* a,
                                         unsigned b0, unsigned b1) {
    asm volatile(
        "mma.sync.aligned.m16n8k8.row.col.f32.tf32.tf32.f32 "
        "{%0,%1,%2,%3}, {%4,%5,%6,%7}, {%8,%9}, {%0,%1,%2,%3};"
        : "+f"(d.x), "+f"(d.y), "+f"(d.z), "+f"(d.w)
        : "r"(a[0]), "r"(a[1]), "r"(a[2]), "r"(a[3]), "r"(b0), "r"(b1));
}

// ----------------------------- GEMM (tf32 tensor cores) ----------------------------
// C[Mx128] = f(A) @ B[Kx128] + bias
//   RELUA:   f = relu(A0)
//   COMBINE: f = attn[0]*relu(A0) + attn[1]*relu(A1)
//   TANH:    A = blockIdx.y ? A1 : A0 (+relu); skip C; colsum[y*128+c] += sum tanh
// 8 warps: wm = warp&3 (32-row band), wn = warp>>2 (64-col band).
// mma m16n8k8 fragment mapping: A a0(g,t) a1(g+8,t) a2(g,t+4) a3(g+8,t+4);
// B b0(t,g) b1(t+4,g); D c0(g,2t) c1(g,2t+1) c2(g+8,2t) c3(g+8,2t+1).
template <int TANH, int RELUA, int COMBINE>
__global__ __launch_bounds__(256)
void sgemm_k(const float* __restrict__ A0, const float* __restrict__ A1,
             const float* __restrict__ attnp,
             const float* __restrict__ B, const float* __restrict__ bias,
             float* __restrict__ C, float* __restrict__ colsum, int M, int K)
{
    __shared__ alignas(16) float As[8][136];   // As[k][row], stride 136 -> no LDS conflicts
    __shared__ alignas(16) float Bs[8][136];   // Bs[k][col]

    const float* A = (TANH && blockIdx.y) ? A1 : A0;
    float* cs = TANH ? colsum + blockIdx.y * 128 : colsum;

    const int tid = threadIdx.x;
    const int lane = tid & 31;
    const int warp = tid >> 5;
    const int wm = warp & 3;
    const int wn = warp >> 2;
    const int g = lane >> 2;
    const int t = lane & 3;
    const int block_row = blockIdx.x * 128;

    const int a_row = tid >> 1;          // 0..127
    const int a_col = (tid & 1) * 4;     // 0 or 4
    const int b_row = tid >> 5;          // 0..7
    const int b_col = (tid & 31) * 4;    // 0..124

    float ca0 = 0.f, ca1 = 0.f;
    if constexpr (COMBINE) { ca0 = __ldg(&attnp[0]); ca1 = __ldg(&attnp[1]); }

    const int gr = block_row + a_row;
    const bool arow_ok = (gr < M);

    float4 d[2][8];
#pragma unroll
    for (int i = 0; i < 2; i++)
#pragma unroll
        for (int j = 0; j < 8; j++) d[i][j] = make_float4(0.f, 0.f, 0.f, 0.f);

    // register-staged tiles (software pipeline)
    float4 av, bv;
    {
        av = make_float4(0.f, 0.f, 0.f, 0.f);
        if (arow_ok) {
            av = *(const float4*)(A + (size_t)gr * K + a_col);
            if constexpr (COMBINE) {
                float4 w2 = *(const float4*)(A1 + (size_t)gr * K + a_col);
                av.x = ca0 * fmaxf(av.x, 0.f) + ca1 * fmaxf(w2.x, 0.f);
                av.y = ca0 * fmaxf(av.y, 0.f) + ca1 * fmaxf(w2.y, 0.f);
                av.z = ca0 * fmaxf(av.z, 0.f) + ca1 * fmaxf(w2.z, 0.f);
                av.w = ca0 * fmaxf(av.w, 0.f) + ca1 * fmaxf(w2.w, 0.f);
            } else if constexpr (RELUA || TANH) {
                av.x = fmaxf(av.x, 0.f); av.y = fmaxf(av.y, 0.f);
                av.z = fmaxf(av.z, 0.f); av.w = fmaxf(av.w, 0.f);
            }
        }
        bv = *(const float4*)(B + (size_t)b_row * 128 + b_col);
    }

    for (int k0 = 0; k0 < K; k0 += 8) {
        As[a_col + 0][a_row] = tfbits(av.x);
        As[a_col + 1][a_row] = tfbits(av.y);
        As[a_col + 2][a_row] = tfbits(av.z);
        As[a_col + 3][a_row] = tfbits(av.w);
        Bs[b_row][b_col + 0] = tfbits(bv.x);
        Bs[b_row][b_col + 1] = tfbits(bv.y);
        Bs[b_row][b_col + 2] = tfbits(bv.z);
        Bs[b_row][b_col + 3] = tfbits(bv.w);
        __syncthreads();

        if (k0 + 8 < K) {   // prefetch next tile (overlaps mma below)
            av = make_float4(0.f, 0.f, 0.f, 0.f);
            if (arow_ok) {
                av = *(const float4*)(A + (size_t)gr * K + k0 + 8 + a_col);
                if constexpr (COMBINE) {
                    float4 w2 = *(const float4*)(A1 + (size_t)gr * K + k0 + 8 + a_col);
                    av.x = ca0 * fmaxf(av.x, 0.f) + ca1 * fmaxf(w2.x, 0.f);
                    av.y = ca0 * fmaxf(av.y, 0.f) + ca1 * fmaxf(w2.y, 0.f);
                    av.z = ca0 * fmaxf(av.z, 0.f) + ca1 * fmaxf(w2.z, 0.f);
                    av.w = ca0 * fmaxf(av.w, 0.f) + ca1 * fmaxf(w2.w, 0.f);
                } else if constexpr (RELUA || TANH) {
                    av.x = fmaxf(av.x, 0.f); av.y = fmaxf(av.y, 0.f);
                    av.z = fmaxf(av.z, 0.f); av.w = fmaxf(av.w, 0.f);
                }
            }
            bv = *(const float4*)(B + (size_t)(k0 + 8 + b_row) * 128 + b_col);
        }

        // A fragments for this warp's two 16-row tiles
        unsigned au[2][4];
#pragma unroll
        for (int mi = 0; mi < 2; mi++) {
            const int rb = wm * 32 + mi * 16 + g;
            au[mi][0] = __float_as_uint(As[t][rb]);
            au[mi][1] = __float_as_uint(As[t][rb + 8]);
            au[mi][2] = __float_as_uint(As[t + 4][rb]);
            au[mi][3] = __float_as_uint(As[t + 4][rb + 8]);
        }
#pragma unroll
        for (int ni = 0; ni < 8; ni++) {
            const int nb = wn * 64 + ni * 8 + g;
            const unsigned b0 = __float_as_uint(Bs[t][nb]);
            const unsigned b1 = __float_as_uint(Bs[t + 4][nb]);
            mma_tf32(d[0][ni], au[0], b0, b1);
            mma_tf32(d[1][ni], au[1], b0, b1);
        }
        __syncthreads();
    }

    // per-thread bias pairs
    float2 bb[8];
#pragma unroll
    for (int ni = 0; ni < 8; ni++) {
        const int c = wn * 64 + ni * 8 + t * 2;
        bb[ni] = make_float2(__ldg(&bias[c]), __ldg(&bias[c + 1]));
    }

    if constexpr (TANH) {
        __shared__ float red[128];
        if (tid < 128) red[tid] = 0.f;
        __syncthreads();
#pragma unroll
        for (int ni = 0; ni < 8; ni++) {
            const int c = wn * 64 + ni * 8 + t * 2;
            float sx = 0.f, sy = 0.f;
#pragma unroll
            for (int mi = 0; mi < 2; mi++) {
                const int r0 = block_row + wm * 32 + mi * 16 + g;
                const int r1 = r0 + 8;
                if (r0 < M) {
                    sx += tanhf(d[mi][ni].x + bb[ni].x);
                    sy += tanhf(d[mi][ni].y + bb[ni].y);
                }
                if (r1 < M) {
                    sx += tanhf(d[mi][ni].z + bb[ni].x);
                    sy += tanhf(d[mi][ni].w + bb[ni].y);
                }
            }
            atomicAdd(&red[c], sx);
            atomicAdd(&red[c + 1], sy);
        }
        __syncthreads();
        if (tid < 128) atomicAdd(&cs[tid], red[tid]);
    } else {
#pragma unroll
        for (int mi = 0; mi < 2; mi++) {
            const int r0 = block_row + wm * 32 + mi * 16 + g;
            const int r1 = r0 + 8;
#pragma unroll
            for (int ni = 0; ni < 8; ni++) {
                const int c = wn * 64 + ni * 8 + t * 2;
                if (r0 < M)
                    *(float2*)(C + (size_t)r0 * 128 + c) =
                        make_float2(d[mi][ni].x + bb[ni].x, d[mi][ni].y + bb[ni].y);
                if (r1 < M)
                    *(float2*)(C + (size_t)r1 * 128 + c) =
                        make_float2(d[mi][ni].z + bb[ni].x, d[mi][ni].w + bb[ni].y);
            }
        }
    }
}

// ----------------------------- multi attention scores (R8-proven) ------------------
struct MS { const float* att[4]; float* out[4]; int nsc; };

__global__ void att_multi_k(const float* __restrict__ xh, MS ms, int N)
{
    const int t = blockIdx.x * blockDim.x + threadIdx.x;
    if (t >= N * 8) return;
    const int n = t >> 3, h = t & 7;
    const float4* xr = (const float4*)(xh + (size_t)n * HID + h * 16);
    float4 x0 = __ldg(&xr[0]), x1 = __ldg(&xr[1]);
    float4 x2 = __ldg(&xr[2]), x3 = __ldg(&xr[3]);
#pragma unroll
    for (int s = 0; s < 4; s++) {
        if (s < ms.nsc) {
            const float4* ar = (const float4*)(ms.att[s] + h * 16);
            float4 a0 = __ldg(&ar[0]), a1 = __ldg(&ar[1]);
            float4 a2 = __ldg(&ar[2]), a3 = __ldg(&ar[3]);
            float r = x0.x * a0.x + x0.y * a0.y + x0.z * a0.z + x0.w * a0.w
                    + x1.x * a1.x + x1.y * a1.y + x1.z * a1.z + x1.w * a1.w
                    + x2.x * a2.x + x2.y * a2.y + x2.z * a2.z + x2.w * a2.w
                    + x3.x * a3.x + x3.y * a3.y + x3.z * a3.z + x3.w * a3.w;
            ms.out[s][t] = r;
        }
    }
}

// ----------------------------- semantic attention weights (M=2) --------------------
__global__ void sem_attn_k(const float* __restrict__ colsum, const float* __restrict__ q,
                           float* __restrict__ attn)
{
    __shared__ float r0[128], r1[128];
    const int t = threadIdx.x;
    const float qv = q[t];
    r0[t] = qv * colsum[t];
    r1[t] = qv * colsum[128 + t];
    __syncthreads();
    for (int s = 64; s > 0; s >>= 1) {
        if (t < s) { r0[t] += r0[t + s]; r1[t] += r1[t + s]; }
        __syncthreads();
    }
    if (t == 0) {
        const float s0 = r0[0] / (float)NP;
        const float s1 = r1[0] / (float)NP;
        const float m = fmaxf(s0, s1);
        const float e0 = __expf(s0 - m), e1 = __expf(s1 - m);
        const float inv = 1.f / (e0 + e1);
        attn[0] = e0 * inv;
        attn[1] = e1 * inv;
    }
}

// ----------------------------- final linear (fused layer-1 combine + relu) ---------
__global__ __launch_bounds__(256)
void final_lin_k(const float* __restrict__ s0, const float* __restrict__ s1,
                 const float* __restrict__ attn, const float* __restrict__ W,
                 const float* __restrict__ b, float* __restrict__ out)
{
    __shared__ float Ws[128 * NCLS];
    for (int i = threadIdx.x; i < 128 * NCLS; i += blockDim.x) Ws[i] = W[i];
    __syncthreads();
    const int n = blockIdx.x * blockDim.x + threadIdx.x;
    if (n >= NP) return;
    const float a0 = __ldg(&attn[0]);
    const float a1 = __ldg(&attn[1]);
    float acc[NCLS];
#pragma unroll
    for (int c = 0; c < NCLS; c++) acc[c] = __ldg(&b[c]);
    const float4* x0 = (const float4*)(s0 + (size_t)n * 128);
    const float4* x1 = (const float4*)(s1 + (size_t)n * 128);
#pragma unroll
    for (int k4 = 0; k4 < 32; k4++) {
        float4 u = __ldg(&x0[k4]);
        float4 v = __ldg(&x1[k4]);
        const float xs[4] = {
            a0 * fmaxf(u.x, 0.f) + a1 * fmaxf(v.x, 0.f),
            a0 * fmaxf(u.y, 0.f) + a1 * fmaxf(v.y, 0.f),
            a0 * fmaxf(u.z, 0.f) + a1 * fmaxf(v.z, 0.f),
            a0 * fmaxf(u.w, 0.f) + a1 * fmaxf(v.w, 0.f)};
#pragma unroll
        for (int uu = 0; uu < 4; uu++) {
            const int k = k4 * 4 + uu;
#pragma unroll
            for (int c = 0; c < NCLS; c++)
                acc[c] = fmaf(xs[uu], Ws[k * NCLS + c], acc[c]);
        }
    }
    float4* op = (float4*)(out + (size_t)n * NCLS);
#pragma unroll
    for (int c4 = 0; c4 < 4; c4++)
        op[c4] = make_float4(acc[c4 * 4], acc[c4 * 4 + 1], acc[c4 * 4 + 2], acc[c4 * 4 + 3]);
}

// ----------------------------- host orchestration ----------------------------------
extern "C" void kernel_launch(void* const* d_in, const int* in_sizes, int n_in,
                              void* d_out, int out_size)
{
    const float* x_author = (const float*)d_in[0];
    const float* x_paper  = (const float*)d_in[1];
    const float* Wa       = (const float*)d_in[2];
    const float* proj_w   = (const float*)d_in[3];
    const float* proj_b   = (const float*)d_in[4];
    const float* att_src  = (const float*)d_in[5];
    const float* att_dst  = (const float*)d_in[6];
    const float* klin_w   = (const float*)d_in[7];
    const float* klin_b   = (const float*)d_in[8];
    const float* q        = (const float*)d_in[9];
    const float* lin_w    = (const float*)d_in[10];
    const float* lin_b    = (const float*)d_in[11];
    const int*   ei_w     = (const int*)d_in[12];
    const int*   ei_wb    = (const int*)d_in[13];
    const int*   ei_c     = (const int*)d_in[14];
    float* out = (float*)d_out;

    float *auth0, *aggA, *xa, *xp, *aggP0, *aggP1;
    float *sa0, *sa1, *sp0, *sp1, *sp2, *sp3, *colsum, *attn0, *attn1, *zb;
    int *rp_w, *rp_wb, *rp_c, *src_w, *src_wb, *src_c, *cnt, *aux;
    cudaGetSymbolAddress((void**)&auth0, g_auth0);
    cudaGetSymbolAddress((void**)&aggA, g_aggA);
    cudaGetSymbolAddress((void**)&xa, g_xa);
    cudaGetSymbolAddress((void**)&xp, g_xp);
    cudaGetSymbolAddress((void**)&aggP0, g_aggP0);
    cudaGetSymbolAddress((void**)&aggP1, g_aggP1);
    cudaGetSymbolAddress((void**)&sa0, g_sa0);
    cudaGetSymbolAddress((void**)&sa1, g_sa1);
    cudaGetSymbolAddress((void**)&sp0, g_sp0);
    cudaGetSymbolAddress((void**)&sp1, g_sp1);
    cudaGetSymbolAddress((void**)&sp2, g_sp2);
    cudaGetSymbolAddress((void**)&sp3, g_sp3);
    cudaGetSymbolAddress((void**)&colsum, g_colsum);
    cudaGetSymbolAddress((void**)&attn0, g_attn0);
    cudaGetSymbolAddress((void**)&attn1, g_attn1);
    cudaGetSymbolAddress((void**)&zb, g_zb);
    cudaGetSymbolAddress((void**)&rp_w, g_rp_w);
    cudaGetSymbolAddress((void**)&rp_wb, g_rp_wb);
    cudaGetSymbolAddress((void**)&rp_c, g_rp_c);
    cudaGetSymbolAddress((void**)&src_w, g_src_w);
    cudaGetSymbolAddress((void**)&src_wb, g_src_wb);
    cudaGetSymbolAddress((void**)&src_c, g_src_c);
    cudaGetSymbolAddress((void**)&cnt, g_cnt);
    cudaGetSymbolAddress((void**)&aux, g_aux);

    int* cnt_w  = cnt;
    int* cnt_wb = cnt + NP;
    int* cnt_c  = cnt + NP + NA;
    int* aux_w  = aux;
    int* aux_wb = aux + 256;
    int* aux_c  = aux + 512;

    const int EB = (EE + 255) / 256;
    const int BW  = (NP + 255) / 256;
    const int BWB = (NA + 255) / 256;

    // ---- CSR build ----
    cudaMemsetAsync(cnt, 0, (2 * NP + NA) * sizeof(int));
    {
        H3 h; h.dst[0] = ei_w + EE; h.dst[1] = ei_wb + EE; h.dst[2] = ei_c + EE;
        h.cnt[0] = cnt_w; h.cnt[1] = cnt_wb; h.cnt[2] = cnt_c;
        hist3_k<<<dim3(EB, 3), 256>>>(h);
    }
    scan_blk_k<<<BW, 256>>>(cnt_w, rp_w, aux_w, NP);
    scan_blk_k<<<BWB, 256>>>(cnt_wb, rp_wb, aux_wb, NA);
    scan_blk_k<<<BW, 256>>>(cnt_c, rp_c, aux_c, NP);
    scan_aux_k<<<1, 256>>>(aux_w, BW);
    scan_aux_k<<<1, 256>>>(aux_wb, BWB);
    scan_aux_k<<<1, 256>>>(aux_c, BW);
    scan_add_k<<<BW, 256>>>(rp_w, aux_w, NP);
    scan_add_k<<<BWB, 256>>>(rp_wb, aux_wb, NA);
    scan_add_k<<<BW, 256>>>(rp_c, aux_c, NP);
    cudaMemsetAsync(cnt, 0, (2 * NP + NA) * sizeof(int));
    {
        S3 s;
        s.ei[0] = ei_w;  s.rowptr[0] = rp_w;  s.cursor[0] = cnt_w;  s.srcs[0] = src_w;
        s.ei[1] = ei_wb; s.rowptr[1] = rp_wb; s.cursor[1] = cnt_wb; s.srcs[1] = src_wb;
        s.ei[2] = ei_c;  s.rowptr[2] = rp_c;  s.cursor[2] = cnt_c;  s.srcs[2] = src_c;
        scatter3_k<<<dim3(EB, 3), 256>>>(s);
    }

    // author raw projection: [20000,64] @ [64,128] (no bias)
    sgemm_k<0, 0, 0><<<(NA + 127) / 128, 256>>>(
        x_author, nullptr, nullptr, Wa, zb, auth0, nullptr, NA, 64);

    // =============================== layer 0 ===============================
    sgemm_k<0, 0, 0><<<(NA + 127) / 128, 256>>>(
        auth0, nullptr, nullptr, proj_w, proj_b, xa, nullptr, NA, 128);
    sgemm_k<0, 0, 0><<<(NP + 127) / 128, 256>>>(
        x_paper, nullptr, nullptr, proj_w + (size_t)128 * 128, proj_b + 128,
        xp, nullptr, NP, 128);

    {   // author scores: writes-src, written_by-dst
        MS ms; ms.nsc = 2;
        ms.att[0] = att_src + 0 * 128; ms.out[0] = sa0;
        ms.att[1] = att_dst + 1 * 128; ms.out[1] = sa1;
        ms.att[2] = ms.att[0]; ms.out[2] = sa0; ms.att[3] = ms.att[0]; ms.out[3] = sa0;
        att_multi_k<<<(NA * 8 + 255) / 256, 256>>>(xa, ms, NA);
    }
    {   // paper scores: writes-dst, wb-src, cites-src, cites-dst
        MS ms; ms.nsc = 4;
        ms.att[0] = att_dst + 0 * 128; ms.out[0] = sp0;
        ms.att[1] = att_src + 1 * 128; ms.out[1] = sp1;
        ms.att[2] = att_src + 2 * 128; ms.out[2] = sp2;
        ms.att[3] = att_dst + 2 * 128; ms.out[3] = sp3;
        att_multi_k<<<(NP * 8 + 255) / 256, 256>>>(xp, ms, NP);
    }

    agg_csr_k<<<(NP * 32 + 255) / 256, 256>>>(rp_w,  src_w,  sa0, sp0, xa, aggP0, NP);
    agg_csr_k<<<(NA * 32 + 255) / 256, 256>>>(rp_wb, src_wb, sp1, sa1, xp, aggA,  NA);
    agg_csr_k<<<(NP * 32 + 255) / 256, 256>>>(rp_c,  src_c,  sp2, sp3, xp, aggP1, NP);

    cudaMemsetAsync(colsum, 0, 2 * 128 * sizeof(float));
    sgemm_k<1, 1, 0><<<dim3((NP + 127) / 128, 2), 256>>>(
        aggP0, aggP1, nullptr, klin_w, klin_b, nullptr, colsum, NP, 128);
    sem_attn_k<<<1, 128>>>(colsum, q, attn0);

    // =============================== layer 1 ===============================
    sgemm_k<0, 1, 0><<<(NA + 127) / 128, 256>>>(
        aggA, nullptr, nullptr, proj_w + (size_t)2 * 128 * 128, proj_b + 2 * 128,
        xa, nullptr, NA, 128);
    sgemm_k<0, 0, 1><<<(NP + 127) / 128, 256>>>(
        aggP0, aggP1, attn0, proj_w + (size_t)3 * 128 * 128, proj_b + 3 * 128,
        xp, nullptr, NP, 128);

    {   // author scores: writes-src
        MS ms; ms.nsc = 1;
        ms.att[0] = att_src + 3 * 128; ms.out[0] = sa0;
        ms.att[1] = ms.att[0]; ms.out[1] = sa0;
        ms.att[2] = ms.att[0]; ms.out[2] = sa0;
        ms.att[3] = ms.att[0]; ms.out[3] = sa0;
        att_multi_k<<<(NA * 8 + 255) / 256, 256>>>(xa, ms, NA);
    }
    {   // paper scores: writes-dst, cites-src, cites-dst
        MS ms; ms.nsc = 3;
        ms.att[0] = att_dst + 3 * 128; ms.out[0] = sp0;
        ms.att[1] = att_src + 5 * 128; ms.out[1] = sp2;
        ms.att[2] = att_dst + 5 * 128; ms.out[2] = sp3;
        ms.att[3] = ms.att[0]; ms.out[3] = sp0;
        att_multi_k<<<(NP * 8 + 255) / 256, 256>>>(xp, ms, NP);
    }

    agg_csr_k<<<(NP * 32 + 255) / 256, 256>>>(rp_w, src_w, sa0, sp0, xa, aggP0, NP);
    agg_csr_k<<<(NP * 32 + 255) / 256, 256>>>(rp_c, src_c, sp2, sp3, xp, aggP1, NP);

    cudaMemsetAsync(colsum, 0, 2 * 128 * sizeof(float));
    sgemm_k<1, 1, 0><<<dim3((NP + 127) / 128, 2), 256>>>(
        aggP0, aggP1, nullptr, klin_w + (size_t)128 * 128, klin_b + 128,
        nullptr, colsum, NP, 128);
    sem_attn_k<<<1, 128>>>(colsum, q + 128, attn1);

    final_lin_k<<<(NP + 255) / 256, 256>>>(aggP0, aggP1, attn1, lin_w, lin_b, out);
}

// round 12
// speedup vs baseline: 3.3773x; 1.0271x over previous
#include <cuda_runtime.h>
#include <cstddef>

#define NA 20000
#define NP 40000
#define EE 400000
#define HID 128
#define NCLS 16

// ----------------------------- scratch (static device globals) -------------------
__device__ float g_auth0[NA * HID];
__device__ float g_aggA[NA * HID];
__device__ float g_xa[NA * HID];
__device__ float g_xp[NP * HID];
__device__ float g_aggP0[NP * HID];
__device__ float g_aggP1[NP * HID];
__device__ float g_sa0[NA * 8];
__device__ float g_sa1[NA * 8];
__device__ float g_sp0[NP * 8];
__device__ float g_sp1[NP * 8];
__device__ float g_sp2[NP * 8];
__device__ float g_sp3[NP * 8];
__device__ float g_colsum[2 * HID];
__device__ float g_attn0[2];
__device__ float g_attn1[2];
__device__ float g_zb[HID];
__device__ int g_rp_w[NP + 1];
__device__ int g_rp_wb[NA + 1];
__device__ int g_rp_c[NP + 1];
__device__ int g_src_w[EE];
__device__ int g_src_wb[EE];
__device__ int g_src_c[EE];
__device__ int g_cnt[NP + NA + NP];
__device__ int g_aux[3 * 256];

// ----------------------------- CSR build -----------------------------------------
struct H3 { const int* dst[3]; int* cnt[3]; };
__global__ void hist3_k(H3 p)
{
    const int y = blockIdx.y;
    const int e = blockIdx.x * blockDim.x + threadIdx.x;
    if (e < EE) atomicAdd(&p.cnt[y][__ldg(&p.dst[y][e])], 1);
}

struct SC3 { const int* cnt[3]; int* rowptr[3]; int* aux[3]; int n[3]; };
__global__ void scan_blk3_k(SC3 p)
{
    const int y = blockIdx.y;
    const int n = p.n[y];
    if (blockIdx.x * 256 >= n) return;
    __shared__ int s[256];
    const int tid = threadIdx.x;
    const int i = blockIdx.x * 256 + tid;
    s[tid] = (i < n) ? p.cnt[y][i] : 0;
    __syncthreads();
#pragma unroll
    for (int off = 1; off < 256; off <<= 1) {
        int t = (tid >= off) ? s[tid - off] : 0;
        __syncthreads();
        s[tid] += t;
        __syncthreads();
    }
    if (i < n) p.rowptr[y][i + 1] = s[tid];
    if (tid == 255) p.aux[y][blockIdx.x] = s[255];
}

struct SA3 { int* aux[3]; int nb[3]; };
__global__ void scan_aux3_k(SA3 p)
{
    const int y = blockIdx.x;
    const int nb = p.nb[y];
    __shared__ int s[256];
    const int tid = threadIdx.x;
    int v = (tid < nb) ? p.aux[y][tid] : 0;
    s[tid] = v;
    __syncthreads();
#pragma unroll
    for (int off = 1; off < 256; off <<= 1) {
        int t = (tid >= off) ? s[tid - off] : 0;
        __syncthreads();
        s[tid] += t;
        __syncthreads();
    }
    if (tid < nb) p.aux[y][tid] = s[tid] - v;
}

struct AD3 { int* rowptr[3]; const int* aux[3]; int n[3]; };
__global__ void scan_add3_k(AD3 p)
{
    const int y = blockIdx.y;
    const int i = blockIdx.x * blockDim.x + threadIdx.x;
    if (i < p.n[y]) p.rowptr[y][i + 1] += p.aux[y][i >> 8];
    if (i == 0) p.rowptr[y][0] = 0;
}

struct S3 { const int* ei[3]; const int* rowptr[3]; int* cursor[3]; int* srcs[3]; };
__global__ void scatter3_k(S3 p)
{
    const int y = blockIdx.y;
    const int e = blockIdx.x * blockDim.x + threadIdx.x;
    if (e >= EE) return;
    const int si = __ldg(&p.ei[y][e]);
    const int di = __ldg(&p.ei[y][EE + e]);
    const int pos = atomicAdd(&p.cursor[y][di], 1);
    p.srcs[y][p.rowptr[y][di] + pos] = si;
}

// ----------------------------- fused CSR aggregation (lane-parallel indices) -------
// One warp per dst node. Indices for up to 32 edges are loaded coalesced by the
// lanes, then shfl-broadcast -> per-edge loads are independent (high MLP).
__global__ __launch_bounds__(256)
void agg_csr_k(const int* __restrict__ rowptr, const int* __restrict__ srcs,
               const float* __restrict__ asrc, const float* __restrict__ adst,
               const float* __restrict__ xh, float* __restrict__ agg, int ndst)
{
    const int w = (blockIdx.x * blockDim.x + threadIdx.x) >> 5;
    if (w >= ndst) return;
    const int lane = threadIdx.x & 31;
    const int h = lane >> 2;
    const int start = __ldg(&rowptr[w]);
    const int end   = __ldg(&rowptr[w + 1]);
    const float ad = __ldg(&adst[(size_t)w * 8 + h]);

    float4 acc = make_float4(0.f, 0.f, 0.f, 0.f);
    float den = 0.f;
    for (int p0 = start; p0 < end; p0 += 32) {
        const int nedge = min(32, end - p0);
        const int myidx = (lane < nedge) ? __ldg(&srcs[p0 + lane]) : 0;
#pragma unroll 4
        for (int j = 0; j < nedge; j++) {
            const int si = __shfl_sync(0xffffffffu, myidx, j);
            float a = __ldg(&asrc[(size_t)si * 8 + h]) + ad;
            a = (a >= 0.f) ? a : 0.2f * a;
            const float e = __expf(a);
            den += e;
            float4 v = __ldg(((const float4*)xh) + (size_t)si * 32 + lane);
            acc.x = fmaf(e, v.x, acc.x);
            acc.y = fmaf(e, v.y, acc.y);
            acc.z = fmaf(e, v.z, acc.z);
            acc.w = fmaf(e, v.w, acc.w);
        }
    }
    const float inv = 1.f / (den + 1e-16f);
    acc.x *= inv; acc.y *= inv; acc.z *= inv; acc.w *= inv;
    ((float4*)agg)[(size_t)w * 32 + lane] = acc;
}

// ----------------------------- tf32 mma helpers ------------------------------------
__device__ __forceinline__ unsigned f2tf(float f) {
    unsigned u;
    asm("cvt.rna.tf32.f32 %0, %1;" : "=r"(u) : "f"(f));
    return u;
}
__device__ __forceinline__ float tfbits(float f) {
    return __uint_as_float(f2tf(f));
}
__device__ __forceinline__ void mma_tf32(float4& d, const unsigned* a,
                                         unsigned b0, unsigned b1) {
    asm volatile(
        "mma.sync.aligned.m16n8k8.row.col.f32.tf32.tf32.f32 "
        "{%0,%1,%2,%3}, {%4,%5,%6,%7}, {%8,%9}, {%0,%1,%2,%3};"
        : "+f"(d.x), "+f"(d.y), "+f"(d.z), "+f"(d.w)
        : "r"(a[0]), "r"(a[1]), "r"(a[2]), "r"(a[3]), "r"(b0), "r"(b1));
}

// ----------------------------- GEMM (tf32, k-tile 16) ------------------------------
// C[Mx128] = f(A) @ B[Kx128] + bias   (variants as before)
template <int TANH, int RELUA, int COMBINE>
__global__ __launch_bounds__(256)
void sgemm_k(const float* __restrict__ A0, const float* __restrict__ A1,
             const float* __restrict__ attnp,
             const float* __restrict__ B, const float* __restrict__ bias,
             float* __restrict__ C, float* __restrict__ colsum, int M, int K)
{
    __shared__ alignas(16) float As[16][136];   // As[k][row]
    __shared__ alignas(16) float Bs[16][136];   // Bs[k][col]

    const float* A = (TANH && blockIdx.y) ? A1 : A0;
    float* cs = TANH ? colsum + blockIdx.y * 128 : colsum;

    const int tid = threadIdx.x;
    const int lane = tid & 31;
    const int warp = tid >> 5;
    const int wm = warp & 3;
    const int wn = warp >> 2;
    const int g = lane >> 2;
    const int t = lane & 3;
    const int block_row = blockIdx.x * 128;

    const int a_row = tid >> 1;          // 0..127
    const int a_col = (tid & 1) * 8;     // 0 or 8
    const int b_row = tid >> 4;          // 0..15
    const int b_col = (tid & 15) * 8;    // 0..120

    float ca0 = 0.f, ca1 = 0.f;
    if constexpr (COMBINE) { ca0 = __ldg(&attnp[0]); ca1 = __ldg(&attnp[1]); }

    const int gr = block_row + a_row;
    const bool arow_ok = (gr < M);

    float4 d[2][8];
#pragma unroll
    for (int i = 0; i < 2; i++)
#pragma unroll
        for (int j = 0; j < 8; j++) d[i][j] = make_float4(0.f, 0.f, 0.f, 0.f);

    float4 av0, av1, bv0, bv1;

    // A-tile loader with fused activation
    auto loadA = [&](int k0, float4& o0, float4& o1) {
        o0 = make_float4(0.f, 0.f, 0.f, 0.f);
        o1 = o0;
        if (arow_ok) {
            o0 = *(const float4*)(A + (size_t)gr * K + k0 + a_col);
            o1 = *(const float4*)(A + (size_t)gr * K + k0 + a_col + 4);
            if constexpr (COMBINE) {
                float4 w0 = *(const float4*)(A1 + (size_t)gr * K + k0 + a_col);
                float4 w1 = *(const float4*)(A1 + (size_t)gr * K + k0 + a_col + 4);
                o0.x = ca0 * fmaxf(o0.x, 0.f) + ca1 * fmaxf(w0.x, 0.f);
                o0.y = ca0 * fmaxf(o0.y, 0.f) + ca1 * fmaxf(w0.y, 0.f);
                o0.z = ca0 * fmaxf(o0.z, 0.f) + ca1 * fmaxf(w0.z, 0.f);
                o0.w = ca0 * fmaxf(o0.w, 0.f) + ca1 * fmaxf(w0.w, 0.f);
                o1.x = ca0 * fmaxf(o1.x, 0.f) + ca1 * fmaxf(w1.x, 0.f);
                o1.y = ca0 * fmaxf(o1.y, 0.f) + ca1 * fmaxf(w1.y, 0.f);
                o1.z = ca0 * fmaxf(o1.z, 0.f) + ca1 * fmaxf(w1.z, 0.f);
                o1.w = ca0 * fmaxf(o1.w, 0.f) + ca1 * fmaxf(w1.w, 0.f);
            } else if constexpr (RELUA || TANH) {
                o0.x = fmaxf(o0.x, 0.f); o0.y = fmaxf(o0.y, 0.f);
                o0.z = fmaxf(o0.z, 0.f); o0.w = fmaxf(o0.w, 0.f);
                o1.x = fmaxf(o1.x, 0.f); o1.y = fmaxf(o1.y, 0.f);
                o1.z = fmaxf(o1.z, 0.f); o1.w = fmaxf(o1.w, 0.f);
            }
        }
    };

    loadA(0, av0, av1);
    bv0 = *(const float4*)(B + (size_t)b_row * 128 + b_col);
    bv1 = *(const float4*)(B + (size_t)b_row * 128 + b_col + 4);

    for (int k0 = 0; k0 < K; k0 += 16) {
        As[a_col + 0][a_row] = tfbits(av0.x);
        As[a_col + 1][a_row] = tfbits(av0.y);
        As[a_col + 2][a_row] = tfbits(av0.z);
        As[a_col + 3][a_row] = tfbits(av0.w);
        As[a_col + 4][a_row] = tfbits(av1.x);
        As[a_col + 5][a_row] = tfbits(av1.y);
        As[a_col + 6][a_row] = tfbits(av1.z);
        As[a_col + 7][a_row] = tfbits(av1.w);
        Bs[b_row][b_col + 0] = tfbits(bv0.x);
        Bs[b_row][b_col + 1] = tfbits(bv0.y);
        Bs[b_row][b_col + 2] = tfbits(bv0.z);
        Bs[b_row][b_col + 3] = tfbits(bv0.w);
        Bs[b_row][b_col + 4] = tfbits(bv1.x);
        Bs[b_row][b_col + 5] = tfbits(bv1.y);
        Bs[b_row][b_col + 6] = tfbits(bv1.z);
        Bs[b_row][b_col + 7] = tfbits(bv1.w);
        __syncthreads();

        if (k0 + 16 < K) {   // prefetch next tile (overlaps mma below)
            loadA(k0 + 16, av0, av1);
            bv0 = *(const float4*)(B + (size_t)(k0 + 16 + b_row) * 128 + b_col);
            bv1 = *(const float4*)(B + (size_t)(k0 + 16 + b_row) * 128 + b_col + 4);
        }

#pragma unroll
        for (int kk = 0; kk < 16; kk += 8) {
            unsigned au[2][4];
#pragma unroll
            for (int mi = 0; mi < 2; mi++) {
                const int rb = wm * 32 + mi * 16 + g;
                au[mi][0] = __float_as_uint(As[kk + t][rb]);
                au[mi][1] = __float_as_uint(As[kk + t][rb + 8]);
                au[mi][2] = __float_as_uint(As[kk + t + 4][rb]);
                au[mi][3] = __float_as_uint(As[kk + t + 4][rb + 8]);
            }
#pragma unroll
            for (int ni = 0; ni < 8; ni++) {
                const int nb = wn * 64 + ni * 8 + g;
                const unsigned b0 = __float_as_uint(Bs[kk + t][nb]);
                const unsigned b1 = __float_as_uint(Bs[kk + t + 4][nb]);
                mma_tf32(d[0][ni], au[0], b0, b1);
                mma_tf32(d[1][ni], au[1], b0, b1);
            }
        }
        __syncthreads();
    }

    float2 bb[8];
#pragma unroll
    for (int ni = 0; ni < 8; ni++) {
        const int c = wn * 64 + ni * 8 + t * 2;
        bb[ni] = make_float2(__ldg(&bias[c]), __ldg(&bias[c + 1]));
    }

    if constexpr (TANH) {
        __shared__ float red[128];
        if (tid < 128) red[tid] = 0.f;
        __syncthreads();
#pragma unroll
        for (int ni = 0; ni < 8; ni++) {
            const int c = wn * 64 + ni * 8 + t * 2;
            float sx = 0.f, sy = 0.f;
#pragma unroll
            for (int mi = 0; mi < 2; mi++) {
                const int r0 = block_row + wm * 32 + mi * 16 + g;
                const int r1 = r0 + 8;
                if (r0 < M) {
                    sx += tanhf(d[mi][ni].x + bb[ni].x);
                    sy += tanhf(d[mi][ni].y + bb[ni].y);
                }
                if (r1 < M) {
                    sx += tanhf(d[mi][ni].z + bb[ni].x);
                    sy += tanhf(d[mi][ni].w + bb[ni].y);
                }
            }
            atomicAdd(&red[c], sx);
            atomicAdd(&red[c + 1], sy);
        }
        __syncthreads();
        if (tid < 128) atomicAdd(&cs[tid], red[tid]);
    } else {
#pragma unroll
        for (int mi = 0; mi < 2; mi++) {
            const int r0 = block_row + wm * 32 + mi * 16 + g;
            const int r1 = r0 + 8;
#pragma unroll
            for (int ni = 0; ni < 8; ni++) {
                const int c = wn * 64 + ni * 8 + t * 2;
                if (r0 < M)
                    *(float2*)(C + (size_t)r0 * 128 + c) =
                        make_float2(d[mi][ni].x + bb[ni].x, d[mi][ni].y + bb[ni].y);
                if (r1 < M)
                    *(float2*)(C + (size_t)r1 * 128 + c) =
                        make_float2(d[mi][ni].z + bb[ni].x, d[mi][ni].w + bb[ni].y);
            }
        }
    }
}

// ----------------------------- multi attention scores ------------------------------
struct MS { const float* att[4]; float* out[4]; int nsc; };

__global__ void att_multi_k(const float* __restrict__ xh, MS ms, int N)
{
    const int t = blockIdx.x * blockDim.x + threadIdx.x;
    if (t >= N * 8) return;
    const int n = t >> 3, h = t & 7;
    const float4* xr = (const float4*)(xh + (size_t)n * HID + h * 16);
    float4 x0 = __ldg(&xr[0]), x1 = __ldg(&xr[1]);
    float4 x2 = __ldg(&xr[2]), x3 = __ldg(&xr[3]);
#pragma unroll
    for (int s = 0; s < 4; s++) {
        if (s < ms.nsc) {
            const float4* ar = (const float4*)(ms.att[s] + h * 16);
            float4 a0 = __ldg(&ar[0]), a1 = __ldg(&ar[1]);
            float4 a2 = __ldg(&ar[2]), a3 = __ldg(&ar[3]);
            float r = x0.x * a0.x + x0.y * a0.y + x0.z * a0.z + x0.w * a0.w
                    + x1.x * a1.x + x1.y * a1.y + x1.z * a1.z + x1.w * a1.w
                    + x2.x * a2.x + x2.y * a2.y + x2.z * a2.z + x2.w * a2.w
                    + x3.x * a3.x + x3.y * a3.y + x3.z * a3.z + x3.w * a3.w;
            ms.out[s][t] = r;
        }
    }
}

// ----------------------------- semantic attention weights (M=2) --------------------
__global__ void sem_attn_k(const float* __restrict__ colsum, const float* __restrict__ q,
                           float* __restrict__ attn)
{
    __shared__ float r0[128], r1[128];
    const int t = threadIdx.x;
    const float qv = q[t];
    r0[t] = qv * colsum[t];
    r1[t] = qv * colsum[128 + t];
    __syncthreads();
    for (int s = 64; s > 0; s >>= 1) {
        if (t < s) { r0[t] += r0[t + s]; r1[t] += r1[t + s]; }
        __syncthreads();
    }
    if (t == 0) {
        const float s0 = r0[0] / (float)NP;
        const float s1 = r1[0] / (float)NP;
        const float m = fmaxf(s0, s1);
        const float e0 = __expf(s0 - m), e1 = __expf(s1 - m);
        const float inv = 1.f / (e0 + e1);
        attn[0] = e0 * inv;
        attn[1] = e1 * inv;
    }
}

// ----------------------------- final linear (fused layer-1 combine + relu) ---------
__global__ __launch_bounds__(256)
void final_lin_k(const float* __restrict__ s0, const float* __restrict__ s1,
                 const float* __restrict__ attn, const float* __restrict__ W,
                 const float* __restrict__ b, float* __restrict__ out)
{
    __shared__ float Ws[128 * NCLS];
    for (int i = threadIdx.x; i < 128 * NCLS; i += blockDim.x) Ws[i] = W[i];
    __syncthreads();
    const int n = blockIdx.x * blockDim.x + threadIdx.x;
    if (n >= NP) return;
    const float a0 = __ldg(&attn[0]);
    const float a1 = __ldg(&attn[1]);
    float acc[NCLS];
#pragma unroll
    for (int c = 0; c < NCLS; c++) acc[c] = __ldg(&b[c]);
    const float4* x0 = (const float4*)(s0 + (size_t)n * 128);
    const float4* x1 = (const float4*)(s1 + (size_t)n * 128);
#pragma unroll
    for (int k4 = 0; k4 < 32; k4++) {
        float4 u = __ldg(&x0[k4]);
        float4 v = __ldg(&x1[k4]);
        const float xs[4] = {
            a0 * fmaxf(u.x, 0.f) + a1 * fmaxf(v.x, 0.f),
            a0 * fmaxf(u.y, 0.f) + a1 * fmaxf(v.y, 0.f),
            a0 * fmaxf(u.z, 0.f) + a1 * fmaxf(v.z, 0.f),
            a0 * fmaxf(u.w, 0.f) + a1 * fmaxf(v.w, 0.f)};
#pragma unroll
        for (int uu = 0; uu < 4; uu++) {
            const int k = k4 * 4 + uu;
#pragma unroll
            for (int c = 0; c < NCLS; c++)
                acc[c] = fmaf(xs[uu], Ws[k * NCLS + c], acc[c]);
        }
    }
    float4* op = (float4*)(out + (size_t)n * NCLS);
#pragma unroll
    for (int c4 = 0; c4 < 4; c4++)
        op[c4] = make_float4(acc[c4 * 4], acc[c4 * 4 + 1], acc[c4 * 4 + 2], acc[c4 * 4 + 3]);
}

// ----------------------------- host orchestration ----------------------------------
extern "C" void kernel_launch(void* const* d_in, const int* in_sizes, int n_in,
                              void* d_out, int out_size)
{
    const float* x_author = (const float*)d_in[0];
    const float* x_paper  = (const float*)d_in[1];
    const float* Wa       = (const float*)d_in[2];
    const float* proj_w   = (const float*)d_in[3];
    const float* proj_b   = (const float*)d_in[4];
    const float* att_src  = (const float*)d_in[5];
    const float* att_dst  = (const float*)d_in[6];
    const float* klin_w   = (const float*)d_in[7];
    const float* klin_b   = (const float*)d_in[8];
    const float* q        = (const float*)d_in[9];
    const float* lin_w    = (const float*)d_in[10];
    const float* lin_b    = (const float*)d_in[11];
    const int*   ei_w     = (const int*)d_in[12];
    const int*   ei_wb    = (const int*)d_in[13];
    const int*   ei_c     = (const int*)d_in[14];
    float* out = (float*)d_out;

    float *auth0, *aggA, *xa, *xp, *aggP0, *aggP1;
    float *sa0, *sa1, *sp0, *sp1, *sp2, *sp3, *colsum, *attn0, *attn1, *zb;
    int *rp_w, *rp_wb, *rp_c, *src_w, *src_wb, *src_c, *cnt, *aux;
    cudaGetSymbolAddress((void**)&auth0, g_auth0);
    cudaGetSymbolAddress((void**)&aggA, g_aggA);
    cudaGetSymbolAddress((void**)&xa, g_xa);
    cudaGetSymbolAddress((void**)&xp, g_xp);
    cudaGetSymbolAddress((void**)&aggP0, g_aggP0);
    cudaGetSymbolAddress((void**)&aggP1, g_aggP1);
    cudaGetSymbolAddress((void**)&sa0, g_sa0);
    cudaGetSymbolAddress((void**)&sa1, g_sa1);
    cudaGetSymbolAddress((void**)&sp0, g_sp0);
    cudaGetSymbolAddress((void**)&sp1, g_sp1);
    cudaGetSymbolAddress((void**)&sp2, g_sp2);
    cudaGetSymbolAddress((void**)&sp3, g_sp3);
    cudaGetSymbolAddress((void**)&colsum, g_colsum);
    cudaGetSymbolAddress((void**)&attn0, g_attn0);
    cudaGetSymbolAddress((void**)&attn1, g_attn1);
    cudaGetSymbolAddress((void**)&zb, g_zb);
    cudaGetSymbolAddress((void**)&rp_w, g_rp_w);
    cudaGetSymbolAddress((void**)&rp_wb, g_rp_wb);
    cudaGetSymbolAddress((void**)&rp_c, g_rp_c);
    cudaGetSymbolAddress((void**)&src_w, g_src_w);
    cudaGetSymbolAddress((void**)&src_wb, g_src_wb);
    cudaGetSymbolAddress((void**)&src_c, g_src_c);
    cudaGetSymbolAddress((void**)&cnt, g_cnt);
    cudaGetSymbolAddress((void**)&aux, g_aux);

    int* cnt_w  = cnt;
    int* cnt_wb = cnt + NP;
    int* cnt_c  = cnt + NP + NA;
    int* aux_w  = aux;
    int* aux_wb = aux + 256;
    int* aux_c  = aux + 512;

    const int EB = (EE + 255) / 256;
    const int BW  = (NP + 255) / 256;   // 157
    const int BWB = (NA + 255) / 256;   // 79

    // ---- CSR build (merged across edge types) ----
    cudaMemsetAsync(cnt, 0, (2 * NP + NA) * sizeof(int));
    {
        H3 h; h.dst[0] = ei_w + EE; h.dst[1] = ei_wb + EE; h.dst[2] = ei_c + EE;
        h.cnt[0] = cnt_w; h.cnt[1] = cnt_wb; h.cnt[2] = cnt_c;
        hist3_k<<<dim3(EB, 3), 256>>>(h);
    }
    {
        SC3 s;
        s.cnt[0] = cnt_w;  s.rowptr[0] = rp_w;  s.aux[0] = aux_w;  s.n[0] = NP;
        s.cnt[1] = cnt_wb; s.rowptr[1] = rp_wb; s.aux[1] = aux_wb; s.n[1] = NA;
        s.cnt[2] = cnt_c;  s.rowptr[2] = rp_c;  s.aux[2] = aux_c;  s.n[2] = NP;
        scan_blk3_k<<<dim3(BW, 3), 256>>>(s);
    }
    {
        SA3 s;
        s.aux[0] = aux_w; s.nb[0] = BW;
        s.aux[1] = aux_wb; s.nb[1] = BWB;
        s.aux[2] = aux_c; s.nb[2] = BW;
        scan_aux3_k<<<3, 256>>>(s);
    }
    {
        AD3 s;
        s.rowptr[0] = rp_w;  s.aux[0] = aux_w;  s.n[0] = NP;
        s.rowptr[1] = rp_wb; s.aux[1] = aux_wb; s.n[1] = NA;
        s.rowptr[2] = rp_c;  s.aux[2] = aux_c;  s.n[2] = NP;
        scan_add3_k<<<dim3(BW, 3), 256>>>(s);
    }
    cudaMemsetAsync(cnt, 0, (2 * NP + NA) * sizeof(int));
    {
        S3 s;
        s.ei[0] = ei_w;  s.rowptr[0] = rp_w;  s.cursor[0] = cnt_w;  s.srcs[0] = src_w;
        s.ei[1] = ei_wb; s.rowptr[1] = rp_wb; s.cursor[1] = cnt_wb; s.srcs[1] = src_wb;
        s.ei[2] = ei_c;  s.rowptr[2] = rp_c;  s.cursor[2] = cnt_c;  s.srcs[2] = src_c;
        scatter3_k<<<dim3(EB, 3), 256>>>(s);
    }

    // author raw projection: [20000,64] @ [64,128] (no bias)
    sgemm_k<0, 0, 0><<<(NA + 127) / 128, 256>>>(
        x_author, nullptr, nullptr, Wa, zb, auth0, nullptr, NA, 64);

    // =============================== layer 0 ===============================
    sgemm_k<0, 0, 0><<<(NA + 127) / 128, 256>>>(
        auth0, nullptr, nullptr, proj_w, proj_b, xa, nullptr, NA, 128);
    sgemm_k<0, 0, 0><<<(NP + 127) / 128, 256>>>(
        x_paper, nullptr, nullptr, proj_w + (size_t)128 * 128, proj_b + 128,
        xp, nullptr, NP, 128);

    {   // author scores: writes-src, written_by-dst
        MS ms; ms.nsc = 2;
        ms.att[0] = att_src + 0 * 128; ms.out[0] = sa0;
        ms.att[1] = att_dst + 1 * 128; ms.out[1] = sa1;
        ms.att[2] = ms.att[0]; ms.out[2] = sa0; ms.att[3] = ms.att[0]; ms.out[3] = sa0;
        att_multi_k<<<(NA * 8 + 255) / 256, 256>>>(xa, ms, NA);
    }
    {   // paper scores: writes-dst, wb-src, cites-src, cites-dst
        MS ms; ms.nsc = 4;
        ms.att[0] = att_dst + 0 * 128; ms.out[0] = sp0;
        ms.att[1] = att_src + 1 * 128; ms.out[1] = sp1;
        ms.att[2] = att_src + 2 * 128; ms.out[2] = sp2;
        ms.att[3] = att_dst + 2 * 128; ms.out[3] = sp3;
        att_multi_k<<<(NP * 8 + 255) / 256, 256>>>(xp, ms, NP);
    }

    agg_csr_k<<<(NP * 32 + 255) / 256, 256>>>(rp_w,  src_w,  sa0, sp0, xa, aggP0, NP);
    agg_csr_k<<<(NA * 32 + 255) / 256, 256>>>(rp_wb, src_wb, sp1, sa1, xp, aggA,  NA);
    agg_csr_k<<<(NP * 32 + 255) / 256, 256>>>(rp_c,  src_c,  sp2, sp3, xp, aggP1, NP);

    cudaMemsetAsync(colsum, 0, 2 * 128 * sizeof(float));
    sgemm_k<1, 1, 0><<<dim3((NP + 127) / 128, 2), 256>>>(
        aggP0, aggP1, nullptr, klin_w, klin_b, nullptr, colsum, NP, 128);
    sem_attn_k<<<1, 128>>>(colsum, q, attn0);

    // =============================== layer 1 ===============================
    sgemm_k<0, 1, 0><<<(NA + 127) / 128, 256>>>(
        aggA, nullptr, nullptr, proj_w + (size_t)2 * 128 * 128, proj_b + 2 * 128,
        xa, nullptr, NA, 128);
    sgemm_k<0, 0, 1><<<(NP + 127) / 128, 256>>>(
        aggP0, aggP1, attn0, proj_w + (size_t)3 * 128 * 128, proj_b + 3 * 128,
        xp, nullptr, NP, 128);

    {   // author scores: writes-src
        MS ms; ms.nsc = 1;
        ms.att[0] = att_src + 3 * 128; ms.out[0] = sa0;
        ms.att[1] = ms.att[0]; ms.out[1] = sa0;
        ms.att[2] = ms.att[0]; ms.out[2] = sa0;
        ms.att[3] = ms.att[0]; ms.out[3] = sa0;
        att_multi_k<<<(NA * 8 + 255) / 256, 256>>>(xa, ms, NA);
    }
    {   // paper scores: writes-dst, cites-src, cites-dst
        MS ms; ms.nsc = 3;
        ms.att[0] = att_dst + 3 * 128; ms.out[0] = sp0;
        ms.att[1] = att_src + 5 * 128; ms.out[1] = sp2;
        ms.att[2] = att_dst + 5 * 128; ms.out[2] = sp3;
        ms.att[3] = ms.att[0]; ms.out[3] = sp0;
        att_multi_k<<<(NP * 8 + 255) / 256, 256>>>(xp, ms, NP);
    }

    agg_csr_k<<<(NP * 32 + 255) / 256, 256>>>(rp_w, src_w, sa0, sp0, xa, aggP0, NP);
    agg_csr_k<<<(NP * 32 + 255) / 256, 256>>>(rp_c, src_c, sp2, sp3, xp, aggP1, NP);

    cudaMemsetAsync(colsum, 0, 2 * 128 * sizeof(float));
    sgemm_k<1, 1, 0><<<dim3((NP + 127) / 128, 2), 256>>>(
        aggP0, aggP1, nullptr, klin_w + (size_t)128 * 128, klin_b + 128,
        nullptr, colsum, NP, 128);
    sem_attn_k<<<1, 128>>>(colsum, q + 128, attn1);

    final_lin_k<<<(NP + 255) / 256, 256>>>(aggP0, aggP1, attn1, lin_w, lin_b, out);
}